// round 1
// baseline (speedup 1.0000x reference)
#include <cuda_runtime.h>
#include <cuda_bf16.h>
#include <cstdint>

// ---------------------------------------------------------------------------
// SSA attention, fp32 baseline.
// Pipeline:
//  1. sgemm_nt : q_raw = x @ WQ^T                  (1024 x 4096)
//  2. sgemm_nt : k_raw = x @ WK^T + bK             (1024 x 512)
//  3. sgemm_nt : v_raw = x @ WV^T + bV             (1024 x 512)
//  4. transform_rope(q): per head h: q' = q(I + M + diag(b_h)), then RoPE
//  5. transform_rope(k): same, k per head from shared head h%8
//  6. blockstats: 16-token block means -> 64x64 block scores -> causal top-8 bitmask
//  7. attn: flash-style online softmax over allowed blocks only (+sink logit)
//  8. sgemm_nn : out = (ctx @ WO_flat + sum_b WO_bias) / 8
// ---------------------------------------------------------------------------

#define T_TOK   1024
#define C_DIM   512
#define HTOT    64
#define NSH     8
#define DH      64
#define NB      64      // number of 16-token blocks
#define BLK     16
#define NEGBIG  (-1e30f)

// scratch (static device allocations are the sanctioned workaround)
__device__ float g_qraw[T_TOK * 4096];
__device__ float g_kraw[T_TOK * C_DIM];
__device__ float g_vraw[T_TOK * C_DIM];
__device__ float g_Q[HTOT * T_TOK * DH];
__device__ float g_K[HTOT * T_TOK * DH];
__device__ float g_ctx[T_TOK * 4096];
__device__ unsigned long long g_mask[HTOT * NB];

// ---------------------------------------------------------------------------
// Generic 128x128x16 SGEMM, 256 threads, 8x8 microtile.
// MODE 0: C = A@B(^T)            MODE 1: C = A@B^T + bias[n]
// MODE 2: C = (A@B + sum8 bias)/8   (output projection + branch mean)
// TRANSB: B is (N x K) row-major (compute A@B^T); else B is (K x N) row-major.
// ---------------------------------------------------------------------------
template<int MODE, bool TRANSB>
__global__ __launch_bounds__(256)
void sgemm128(const float* __restrict__ Ag, const float* __restrict__ Bg,
              const float* __restrict__ bias, float* __restrict__ Cg,
              int M, int N, int K)
{
    __shared__ float As[16][128];
    __shared__ float Bs[16][128];
    int tid = threadIdx.x;
    int tx = tid & 15, ty = tid >> 4;
    int m0 = blockIdx.y * 128, n0 = blockIdx.x * 128;
    float acc[8][8];
#pragma unroll
    for (int i = 0; i < 8; ++i)
#pragma unroll
        for (int j = 0; j < 8; ++j) acc[i][j] = 0.f;

    for (int k0 = 0; k0 < K; k0 += 16) {
#pragma unroll
        for (int q = 0; q < 2; ++q) {
            int idx = q * 256 + tid;
            int row = idx >> 2;
            int kq  = (idx & 3) << 2;
            float4 a = *reinterpret_cast<const float4*>(Ag + (size_t)(m0 + row) * K + k0 + kq);
            As[kq + 0][row] = a.x; As[kq + 1][row] = a.y;
            As[kq + 2][row] = a.z; As[kq + 3][row] = a.w;
        }
        if (TRANSB) {
#pragma unroll
            for (int q = 0; q < 2; ++q) {
                int idx = q * 256 + tid;
                int row = idx >> 2;
                int kq  = (idx & 3) << 2;
                float4 b = *reinterpret_cast<const float4*>(Bg + (size_t)(n0 + row) * K + k0 + kq);
                Bs[kq + 0][row] = b.x; Bs[kq + 1][row] = b.y;
                Bs[kq + 2][row] = b.z; Bs[kq + 3][row] = b.w;
            }
        } else {
#pragma unroll
            for (int q = 0; q < 2; ++q) {
                int idx = q * 256 + tid;
                int r = idx >> 5;
                int c = (idx & 31) << 2;
                *reinterpret_cast<float4*>(&Bs[r][c]) =
                    *reinterpret_cast<const float4*>(Bg + (size_t)(k0 + r) * N + n0 + c);
            }
        }
        __syncthreads();
#pragma unroll
        for (int kk = 0; kk < 16; ++kk) {
            float af[8], bf[8];
            *reinterpret_cast<float4*>(af)     = *reinterpret_cast<float4*>(&As[kk][ty * 8]);
            *reinterpret_cast<float4*>(af + 4) = *reinterpret_cast<float4*>(&As[kk][ty * 8 + 4]);
            *reinterpret_cast<float4*>(bf)     = *reinterpret_cast<float4*>(&Bs[kk][tx * 8]);
            *reinterpret_cast<float4*>(bf + 4) = *reinterpret_cast<float4*>(&Bs[kk][tx * 8 + 4]);
#pragma unroll
            for (int i = 0; i < 8; ++i)
#pragma unroll
                for (int j = 0; j < 8; ++j) acc[i][j] += af[i] * bf[j];
        }
        __syncthreads();
    }

#pragma unroll
    for (int i = 0; i < 8; ++i) {
        int m = m0 + ty * 8 + i;
#pragma unroll
        for (int j = 0; j < 8; ++j) {
            int n = n0 + tx * 8 + j;
            float v = acc[i][j];
            if (MODE == 1) v += bias[n];
            if (MODE == 2) {
                float bs = 0.f;
#pragma unroll
                for (int b8 = 0; b8 < 8; ++b8) bs += bias[b8 * N + n];
                v = 0.125f * (v + bs);
            }
            Cg[(size_t)m * N + n] = v;
        }
    }
}

// ---------------------------------------------------------------------------
// Per-head S-transform + RoPE.
//   c[e] = r[e]*(1 + b_h[e]) + sum_d r[d]*(A[d][e]-A[e][d])
//   out[f]    = c[2f]*cos - c[2f+1]*sin ; out[f+32] = c[2f]*sin + c[2f+1]*cos
// One CTA = (head, 64 tokens). Thread owns (token, 16 contiguous dims) so the
// rope stage consumes exactly its own computed values (no second smem tile).
// ---------------------------------------------------------------------------
__global__ __launch_bounds__(256)
void transform_rope_kernel(const float* __restrict__ raw, int src_stride, int is_q,
                           const float* __restrict__ Amat, const float* __restrict__ id_bias,
                           float* __restrict__ outp)
{
    int h  = blockIdx.x;
    int t0 = blockIdx.y * 64;
    int tid = threadIdx.x;
    __shared__ float Msm[64][64];
    __shared__ float rsm[64][65];
    __shared__ float invf_s[32];

    if (tid < 32) invf_s[tid] = (float)exp(-9.210340371976184 * (double)tid / 32.0);

    int off = is_q ? h * 64 : (h & 7) * 64;
    for (int idx = tid; idx < 4096; idx += 256) {
        int d = idx >> 6, e = idx & 63;
        Msm[d][e] = Amat[d * 64 + e] - Amat[e * 64 + d];
    }
    for (int idx = tid; idx < 4096; idx += 256) {
        int tok = idx >> 6, d = idx & 63;
        rsm[tok][d] = raw[(size_t)(t0 + tok) * src_stride + off + d];
    }
    __syncthreads();

    int tok = tid >> 2;
    int e0  = (tid & 3) * 16;
    float cv[16];
#pragma unroll
    for (int e = 0; e < 16; ++e) cv[e] = 0.f;
    for (int d = 0; d < 64; ++d) {
        float rv = rsm[tok][d];
#pragma unroll
        for (int e = 0; e < 16; ++e) cv[e] += rv * Msm[d][e0 + e];
    }
#pragma unroll
    for (int e = 0; e < 16; ++e) {
        float be = id_bias[h * 64 + e0 + e];
        cv[e] = rsm[tok][e0 + e] * (1.f + be) + cv[e];
    }

    // rope: this thread's e-range [e0, e0+16) = freq indices [e0/2, e0/2+8)
    int f0 = (tid & 3) * 8;
    float tval = (float)(t0 + tok);
    float* orow = outp + ((size_t)h * T_TOK + t0 + tok) * 64;
#pragma unroll
    for (int fl = 0; fl < 8; ++fl) {
        int f = f0 + fl;
        float ang = tval * invf_s[f];
        float cs = cosf(ang), sn = sinf(ang);
        float x1 = cv[2 * fl], x2 = cv[2 * fl + 1];
        orow[f]      = x1 * cs - x2 * sn;
        orow[f + 32] = x1 * sn + x2 * cs;
    }
}

// ---------------------------------------------------------------------------
// Block means -> block scores -> causal top-8 bitmask per (head, query block).
// One CTA per head. 48KB smem exactly.
// ---------------------------------------------------------------------------
__global__ __launch_bounds__(256)
void blockstats_kernel(const float* __restrict__ Q, const float* __restrict__ K,
                       unsigned long long* __restrict__ maskbits)
{
    int h = blockIdx.x, tid = threadIdx.x;
    __shared__ float qm[64][64];
    __shared__ float kmT[64][64];   // transposed: kmT[d][block]
    __shared__ float sc[64][64];

    for (int idx = tid; idx < 4096; idx += 256) {
        int blk = idx >> 6, d = idx & 63;
        const float* Qp = Q + ((size_t)h * T_TOK + blk * 16) * 64 + d;
        const float* Kp = K + ((size_t)h * T_TOK + blk * 16) * 64 + d;
        float sq = 0.f, sk = 0.f;
#pragma unroll
        for (int l = 0; l < 16; ++l) { sq += Qp[l * 64]; sk += Kp[l * 64]; }
        qm[blk][d] = sq * 0.0625f;
        kmT[d][blk] = sk * 0.0625f;
    }
    __syncthreads();
    for (int idx = tid; idx < 4096; idx += 256) {
        int r = idx >> 6, c = idx & 63;
        float s = 0.f;
#pragma unroll
        for (int d = 0; d < 64; ++d) s += qm[r][d] * kmT[d][c];
        sc[r][c] = s;
    }
    __syncthreads();
    if (tid < 64) {
        int r = tid;
        unsigned long long bits = 0ull;
        int nsel = (r + 1 < 8) ? (r + 1) : 8;
        for (int sel = 0; sel < nsel; ++sel) {
            float best = -1e38f; int bi = 0;
            for (int kb = 0; kb <= r; ++kb) {
                float v = sc[r][kb];
                if (v > best) { best = v; bi = kb; }
            }
            sc[r][bi] = -1e38f;
            bits |= (1ull << bi);
        }
        maskbits[h * NB + r] = bits;
    }
}

// ---------------------------------------------------------------------------
// Sparse flash attention. CTA = (head, 16-query block), 256 threads.
// thread (qi,kj) owns score (qi,kj) and ctx dims [kj*4, kj*4+4) of row qi.
// Visits key block kb iff top-8 | sink(kb<4) | self(kb==qb) | band(kb==qb-1).
// Within top-8/sink/self blocks only causality applies; band block qb-1 is
// additionally token-gated by j >= i-16. Sink logit folded in at the end.
// ---------------------------------------------------------------------------
__global__ __launch_bounds__(256)
void attn_kernel(const float* __restrict__ Q, const float* __restrict__ K,
                 const float* __restrict__ V, const unsigned long long* __restrict__ maskbits,
                 const float* __restrict__ sink_scalars, const float* __restrict__ v_nulls,
                 float* __restrict__ ctx)
{
    int h = blockIdx.x, qb = blockIdx.y;
    int tid = threadIdx.x;
    int qi = tid >> 4, kj = tid & 15;
    int s = h & 7;
    __shared__ float qs[16][65], ks[16][65];
    __shared__ float vs[16][64];
    __shared__ float ps[16][17];

    const float* Qh = Q + ((size_t)h * T_TOK + qb * 16) * 64;
    for (int i = tid; i < 1024; i += 256) qs[i >> 6][i & 63] = Qh[i];
    __syncthreads();

    unsigned long long bm = maskbits[h * NB + qb];
    float m = NEGBIG, l = 0.f;
    float a0 = 0.f, a1 = 0.f, a2 = 0.f, a3 = 0.f;
    int itok = qb * 16 + qi;

    for (int kb = 0; kb <= qb; ++kb) {
        bool blk_ok = ((bm >> kb) & 1ull) || (kb < 4) || (kb == qb);
        if (!blk_ok && kb != qb - 1) continue;

        const float* Kh = K + ((size_t)h * T_TOK + kb * 16) * 64;
        const float* Vh = V + (size_t)(kb * 16) * C_DIM + s * 64;
        for (int i = tid; i < 1024; i += 256) ks[i >> 6][i & 63] = Kh[i];
        for (int i = tid; i < 1024; i += 256) vs[i >> 6][i & 63] = Vh[(i >> 6) * C_DIM + (i & 63)];
        __syncthreads();

        float scv = 0.f;
#pragma unroll
        for (int d = 0; d < 64; ++d) scv += qs[qi][d] * ks[kj][d];
        scv *= 0.125f;  // DH^-0.5

        int j = kb * 16 + kj;
        bool valid = (j <= itok) && (blk_ok || (j >= itok - 16));
        if (!valid) scv = NEGBIG;

        float mx = scv;
#pragma unroll
        for (int o = 8; o; o >>= 1) mx = fmaxf(mx, __shfl_xor_sync(0xffffffffu, mx, o, 16));
        float mn = fmaxf(m, mx);
        float alpha = __expf(m - mn);
        float p = __expf(scv - mn);
        float pr = p;
#pragma unroll
        for (int o = 8; o; o >>= 1) pr += __shfl_xor_sync(0xffffffffu, pr, o, 16);
        l = l * alpha + pr;
        m = mn;
        ps[qi][kj] = p;
        __syncthreads();

        a0 *= alpha; a1 *= alpha; a2 *= alpha; a3 *= alpha;
#pragma unroll
        for (int k2 = 0; k2 < 16; ++k2) {
            float pv = ps[qi][k2];
            float4 vv = *reinterpret_cast<const float4*>(&vs[k2][kj * 4]);
            a0 += pv * vv.x; a1 += pv * vv.y; a2 += pv * vv.z; a3 += pv * vv.w;
        }
        __syncthreads();
    }

    // fold in the sink logit
    float sv = sink_scalars[h];
    float mn = fmaxf(m, sv);
    float alpha = __expf(m - mn);
    float pk = __expf(sv - mn);
    l = l * alpha + pk;
    float inv = 1.f / l;
    const float* vn = v_nulls + h * 64 + kj * 4;
    float* op = ctx + (size_t)itok * 4096 + h * 64 + kj * 4;
    op[0] = (a0 * alpha + pk * vn[0]) * inv;
    op[1] = (a1 * alpha + pk * vn[1]) * inv;
    op[2] = (a2 * alpha + pk * vn[2]) * inv;
    op[3] = (a3 * alpha + pk * vn[3]) * inv;
}

// ---------------------------------------------------------------------------
extern "C" void kernel_launch(void* const* d_in, const int* in_sizes, int n_in,
                              void* d_out, int out_size)
{
    const float* x   = (const float*)d_in[0];
    const float* WQ  = (const float*)d_in[1];
    const float* WK  = (const float*)d_in[2];
    const float* bK  = (const float*)d_in[3];
    const float* WV  = (const float*)d_in[4];
    const float* bV  = (const float*)d_in[5];
    const float* Am  = (const float*)d_in[6];
    const float* idb = (const float*)d_in[7];
    const float* snk = (const float*)d_in[8];
    const float* vnl = (const float*)d_in[9];
    const float* WO  = (const float*)d_in[10];
    const float* WOb = (const float*)d_in[11];
    float* out = (float*)d_out;

    float *qraw, *kraw, *vraw, *Qb, *Kb, *ctx;
    unsigned long long* mb;
    cudaGetSymbolAddress((void**)&qraw, g_qraw);
    cudaGetSymbolAddress((void**)&kraw, g_kraw);
    cudaGetSymbolAddress((void**)&vraw, g_vraw);
    cudaGetSymbolAddress((void**)&Qb,   g_Q);
    cudaGetSymbolAddress((void**)&Kb,   g_K);
    cudaGetSymbolAddress((void**)&ctx,  g_ctx);
    cudaGetSymbolAddress((void**)&mb,   g_mask);

    // 1-3: projections
    sgemm128<0, true><<<dim3(32, 8), 256>>>(x, WQ, nullptr, qraw, 1024, 4096, 512);
    sgemm128<1, true><<<dim3(4, 8), 256>>>(x, WK, bK, kraw, 1024, 512, 512);
    sgemm128<1, true><<<dim3(4, 8), 256>>>(x, WV, bV, vraw, 1024, 512, 512);

    // 4-5: per-head S transform + rope
    transform_rope_kernel<<<dim3(64, 16), 256>>>(qraw, 4096, 1, Am, idb, Qb);
    transform_rope_kernel<<<dim3(64, 16), 256>>>(kraw, 512, 0, Am, idb, Kb);

    // 6: block top-k mask
    blockstats_kernel<<<64, 256>>>(Qb, Kb, mb);

    // 7: sparse attention
    attn_kernel<<<dim3(64, 64), 256>>>(Qb, Kb, vraw, mb, snk, vnl, ctx);

    // 8: output projection + branch mean
    sgemm128<2, false><<<dim3(4, 8), 256>>>(ctx, WO, WOb, out, 1024, 512, 4096);
}

// round 5
// speedup vs baseline: 1.6640x; 1.6640x over previous
#include <cuda_runtime.h>
#include <cuda_bf16.h>
#include <cstdint>

// ---------------------------------------------------------------------------
// SSA attention, 3xTF32 tensor-core pipeline.  (r5: identical to r4; r4 died
// to container infra, not kernel — resubmitted for a clean measurement)
//  prep_misc : bias vector [0 | bKeff | bV], copy WV into Weff tail
//  prep_fold : Weff rows = per-head T_h^T @ W_blk   (3xTF32 accurate)
//  mma_gemm<X3=1> : raw(1024x8704) = x @ Weff^T + bias
//  rope      : split raw -> Q[h][t][d], K[h][t][d] with RoPE
//  blockstats: block means -> 64x64 scores -> causal top-8 bitmask
//  attn      : sparse flash attention (+sink), fp32
//  mma_gemm<X3=0> : split-K=4 partials of ctx @ WO_flat
//  reduce_out: mean over splits + bias/8
// ---------------------------------------------------------------------------

#define T_TOK   1024
#define NB      64
#define NEGBIG  (-1e30f)
#define NRAW    8704          // 4096 q + 4096 k + 512 v

__device__ float g_Weff[NRAW * 512];
__device__ float g_bias[NRAW];
__device__ float g_raw[T_TOK * NRAW];
__device__ float g_Q[64 * T_TOK * 64];
__device__ float g_K[64 * T_TOK * 64];
__device__ float g_ctx[T_TOK * 4096];
__device__ float g_part[4 * T_TOK * 512];
__device__ unsigned long long g_mask[64 * NB];

__device__ __forceinline__ float tf32r(float x) {
    uint32_t u;
    asm("cvt.rna.tf32.f32 %0, %1;" : "=r"(u) : "f"(x));
    return __uint_as_float(u);
}

__device__ __forceinline__ void mma8(float* c, const uint32_t* a, const uint32_t* b) {
    asm volatile(
        "mma.sync.aligned.m16n8k8.row.col.f32.tf32.tf32.f32 "
        "{%0,%1,%2,%3}, {%4,%5,%6,%7}, {%8,%9}, {%0,%1,%2,%3};"
        : "+f"(c[0]), "+f"(c[1]), "+f"(c[2]), "+f"(c[3])
        : "r"(a[0]), "r"(a[1]), "r"(a[2]), "r"(a[3]), "r"(b[0]), "r"(b[1]));
}

// ---------------------------------------------------------------------------
// misc prep: bias vector + WV copy into Weff tail (all exact fp32)
// ---------------------------------------------------------------------------
__global__ void prep_misc(const float* __restrict__ A, const float* __restrict__ idb,
                          const float* __restrict__ bK, const float* __restrict__ bV,
                          const float* __restrict__ WV,
                          float* __restrict__ Weff, float* __restrict__ biasv)
{
    int idx = blockIdx.x * 256 + threadIdx.x;
    if (idx < 262144) Weff[8192 * 512 + idx] = WV[idx];
    if (idx < 4096) {
        biasv[idx] = 0.f;
        int h = idx >> 6, e = idx & 63, s = h & 7;
        float acc = (1.f + idb[idx]) * bK[s * 64 + e];
        for (int d = 0; d < 64; ++d)
            acc += (A[d * 64 + e] - A[e * 64 + d]) * bK[s * 64 + d];
        biasv[4096 + idx] = acc;
    }
    if (idx < 512) biasv[8192 + idx] = bV[idx];
}

// ---------------------------------------------------------------------------
// Weight folding, 3xTF32: Weff[e,c] = sum_d T_h[d,e] * Wsrc[d,c]
//   T_h = (A - A^T) + diag(1 + id_bias[h])
// grid (2 parts, 64 heads), 128 threads. Streams W in 32-col chunks.
// smem: Th/Tl 64x64 (32KB) + Wh/Wl 64x32 (16KB) = 48KB static exactly.
// ---------------------------------------------------------------------------
__global__ __launch_bounds__(128)
void prep_fold(const float* __restrict__ A, const float* __restrict__ idb,
               const float* __restrict__ WQ, const float* __restrict__ WK,
               float* __restrict__ Weff)
{
    int part = blockIdx.x, h = blockIdx.y;
    int tid = threadIdx.x;
    int warp = tid >> 5, lane = tid & 31;
    int g = lane >> 2, tg = lane & 3;
    __shared__ float Th[64][64], Tl[64][64];   // Tt[e][d] = T[d][e]
    __shared__ float Wh[64][32], Wl[64][32];
    int s = h & 7;

    for (int idx = tid; idx < 4096; idx += 128) {
        int e = idx >> 6, d = idx & 63;
        float v = A[d * 64 + e] - A[e * 64 + d];
        if (d == e) v += 1.f + idb[h * 64 + e];
        float hi = tf32r(v);
        Th[e][d] = hi;
        Tl[e][d] = tf32r(v - hi);
    }
    const float* Wsrc = part ? (WK + (size_t)(s * 64) * 512) : (WQ + (size_t)(h * 64) * 512);
    float* Wdst = Weff + (size_t)(part * 4096 + h * 64) * 512;

    for (int chunk = 0; chunk < 16; ++chunk) {
        __syncthreads();
        for (int idx = tid; idx < 2048; idx += 128) {
            int d = idx >> 5, n = idx & 31;
            float v = Wsrc[(size_t)d * 512 + chunk * 32 + n];
            float hi = tf32r(v);
            Wh[d][n] = hi;
            Wl[d][n] = tf32r(v - hi);
        }
        __syncthreads();

        float c[4][4];
#pragma unroll
        for (int mt = 0; mt < 4; ++mt)
#pragma unroll
            for (int r = 0; r < 4; ++r) c[mt][r] = 0.f;

#pragma unroll
        for (int k0 = 0; k0 < 64; k0 += 8) {
            uint32_t ah[4][4], al[4][4], bh[2], bl[2];
#pragma unroll
            for (int mt = 0; mt < 4; ++mt) {
                int mb = mt * 16;
                ah[mt][0] = __float_as_uint(Th[mb + g][k0 + tg]);
                ah[mt][1] = __float_as_uint(Th[mb + g + 8][k0 + tg]);
                ah[mt][2] = __float_as_uint(Th[mb + g][k0 + tg + 4]);
                ah[mt][3] = __float_as_uint(Th[mb + g + 8][k0 + tg + 4]);
                al[mt][0] = __float_as_uint(Tl[mb + g][k0 + tg]);
                al[mt][1] = __float_as_uint(Tl[mb + g + 8][k0 + tg]);
                al[mt][2] = __float_as_uint(Tl[mb + g][k0 + tg + 4]);
                al[mt][3] = __float_as_uint(Tl[mb + g + 8][k0 + tg + 4]);
            }
            int nb = warp * 8;
            bh[0] = __float_as_uint(Wh[k0 + tg][nb + g]);
            bh[1] = __float_as_uint(Wh[k0 + tg + 4][nb + g]);
            bl[0] = __float_as_uint(Wl[k0 + tg][nb + g]);
            bl[1] = __float_as_uint(Wl[k0 + tg + 4][nb + g]);
#pragma unroll
            for (int mt = 0; mt < 4; ++mt) {
                mma8(c[mt], ah[mt], bh);
                mma8(c[mt], ah[mt], bl);
                mma8(c[mt], al[mt], bh);
            }
        }
#pragma unroll
        for (int mt = 0; mt < 4; ++mt) {
            int row = mt * 16 + g;
            int col = chunk * 32 + warp * 8 + 2 * tg;
            *reinterpret_cast<float2*>(Wdst + (size_t)row * 512 + col)
                = make_float2(c[mt][0], c[mt][1]);
            *reinterpret_cast<float2*>(Wdst + (size_t)(row + 8) * 512 + col)
                = make_float2(c[mt][2], c[mt][3]);
        }
    }
}

// ---------------------------------------------------------------------------
// tf32 mma GEMM: C(MxN) = A(MxK) @ B(^T).  128x128 tile, 256 thr, 8 warps.
// X3: 3xTF32 error-compensated (hi/lo split, 3 mmas per product).
// ---------------------------------------------------------------------------
template<bool TRANSB, bool ADD_BIAS, int SPLITK, bool X3>
__global__ __launch_bounds__(256)
void mma_gemm(const float* __restrict__ Ag, const float* __restrict__ Bg,
              const float* __restrict__ bias, float* __restrict__ Cg,
              int M, int N, int K)
{
    __shared__ float Ah[16][132], Bh[16][132];
    __shared__ float Al[16][132], Bl[16][132];
    int tid = threadIdx.x;
    int warp = tid >> 5, lane = tid & 31;
    int wm = warp >> 2, wn = warp & 3;
    int g = lane >> 2, tg = lane & 3;
    int m0 = blockIdx.y * 128, n0 = blockIdx.x * 128;
    int kchunk = K / SPLITK;
    int kbeg = blockIdx.z * kchunk;
    int kend = kbeg + kchunk;

    float c[4][4][4];
#pragma unroll
    for (int i = 0; i < 4; ++i)
#pragma unroll
        for (int j = 0; j < 4; ++j)
#pragma unroll
            for (int r = 0; r < 4; ++r) c[i][j][r] = 0.f;

    for (int k0 = kbeg; k0 < kend; k0 += 16) {
#pragma unroll
        for (int q = 0; q < 2; ++q) {
            int idx = q * 256 + tid;
            int row = idx >> 2, kq = (idx & 3) << 2;
            float4 a = *reinterpret_cast<const float4*>(Ag + (size_t)(m0 + row) * K + k0 + kq);
            float h0 = tf32r(a.x), h1 = tf32r(a.y), h2 = tf32r(a.z), h3 = tf32r(a.w);
            Ah[kq + 0][row] = h0; Ah[kq + 1][row] = h1;
            Ah[kq + 2][row] = h2; Ah[kq + 3][row] = h3;
            if (X3) {
                Al[kq + 0][row] = tf32r(a.x - h0); Al[kq + 1][row] = tf32r(a.y - h1);
                Al[kq + 2][row] = tf32r(a.z - h2); Al[kq + 3][row] = tf32r(a.w - h3);
            }
        }
        if (TRANSB) {
#pragma unroll
            for (int q = 0; q < 2; ++q) {
                int idx = q * 256 + tid;
                int row = idx >> 2, kq = (idx & 3) << 2;
                float4 b = *reinterpret_cast<const float4*>(Bg + (size_t)(n0 + row) * K + k0 + kq);
                float h0 = tf32r(b.x), h1 = tf32r(b.y), h2 = tf32r(b.z), h3 = tf32r(b.w);
                Bh[kq + 0][row] = h0; Bh[kq + 1][row] = h1;
                Bh[kq + 2][row] = h2; Bh[kq + 3][row] = h3;
                if (X3) {
                    Bl[kq + 0][row] = tf32r(b.x - h0); Bl[kq + 1][row] = tf32r(b.y - h1);
                    Bl[kq + 2][row] = tf32r(b.z - h2); Bl[kq + 3][row] = tf32r(b.w - h3);
                }
            }
        } else {
#pragma unroll
            for (int q = 0; q < 2; ++q) {
                int idx = q * 256 + tid;
                int r = idx >> 5, ccol = (idx & 31) << 2;
                float4 b = *reinterpret_cast<const float4*>(Bg + (size_t)(k0 + r) * N + n0 + ccol);
                float h0 = tf32r(b.x), h1 = tf32r(b.y), h2 = tf32r(b.z), h3 = tf32r(b.w);
                Bh[r][ccol + 0] = h0; Bh[r][ccol + 1] = h1;
                Bh[r][ccol + 2] = h2; Bh[r][ccol + 3] = h3;
                if (X3) {
                    Bl[r][ccol + 0] = tf32r(b.x - h0); Bl[r][ccol + 1] = tf32r(b.y - h1);
                    Bl[r][ccol + 2] = tf32r(b.z - h2); Bl[r][ccol + 3] = tf32r(b.w - h3);
                }
            }
        }
        __syncthreads();
#pragma unroll
        for (int h8 = 0; h8 < 16; h8 += 8) {
            uint32_t afh[4][4], bfh[4][2];
            uint32_t afl[4][4], bfl[4][2];
#pragma unroll
            for (int mt = 0; mt < 4; ++mt) {
                int mb = wm * 64 + mt * 16;
                afh[mt][0] = __float_as_uint(Ah[h8 + tg][mb + g]);
                afh[mt][1] = __float_as_uint(Ah[h8 + tg][mb + g + 8]);
                afh[mt][2] = __float_as_uint(Ah[h8 + tg + 4][mb + g]);
                afh[mt][3] = __float_as_uint(Ah[h8 + tg + 4][mb + g + 8]);
                if (X3) {
                    afl[mt][0] = __float_as_uint(Al[h8 + tg][mb + g]);
                    afl[mt][1] = __float_as_uint(Al[h8 + tg][mb + g + 8]);
                    afl[mt][2] = __float_as_uint(Al[h8 + tg + 4][mb + g]);
                    afl[mt][3] = __float_as_uint(Al[h8 + tg + 4][mb + g + 8]);
                }
            }
#pragma unroll
            for (int nt = 0; nt < 4; ++nt) {
                int nb = wn * 32 + nt * 8;
                bfh[nt][0] = __float_as_uint(Bh[h8 + tg][nb + g]);
                bfh[nt][1] = __float_as_uint(Bh[h8 + tg + 4][nb + g]);
                if (X3) {
                    bfl[nt][0] = __float_as_uint(Bl[h8 + tg][nb + g]);
                    bfl[nt][1] = __float_as_uint(Bl[h8 + tg + 4][nb + g]);
                }
            }
#pragma unroll
            for (int mt = 0; mt < 4; ++mt)
#pragma unroll
                for (int nt = 0; nt < 4; ++nt) {
                    mma8(c[mt][nt], afh[mt], bfh[nt]);
                    if (X3) {
                        mma8(c[mt][nt], afh[mt], bfl[nt]);
                        mma8(c[mt][nt], afl[mt], bfh[nt]);
                    }
                }
        }
        __syncthreads();
    }

    float* Cp = Cg + (SPLITK > 1 ? (size_t)blockIdx.z * M * N : 0);
#pragma unroll
    for (int mt = 0; mt < 4; ++mt) {
        int row = m0 + wm * 64 + mt * 16 + g;
#pragma unroll
        for (int nt = 0; nt < 4; ++nt) {
            int col = n0 + wn * 32 + nt * 8 + 2 * tg;
            float b0 = 0.f, b1 = 0.f;
            if (ADD_BIAS) { b0 = bias[col]; b1 = bias[col + 1]; }
            *reinterpret_cast<float2*>(Cp + (size_t)row * N + col)
                = make_float2(c[mt][nt][0] + b0, c[mt][nt][1] + b1);
            *reinterpret_cast<float2*>(Cp + (size_t)(row + 8) * N + col)
                = make_float2(c[mt][nt][2] + b0, c[mt][nt][3] + b1);
        }
    }
}

// ---------------------------------------------------------------------------
// RoPE split: raw(t, 8704) -> Q[h][t][64], K[h][t][64]
// ---------------------------------------------------------------------------
__global__ __launch_bounds__(256)
void rope_kernel(const float* __restrict__ raw, float* __restrict__ Qo, float* __restrict__ Ko)
{
    int h = blockIdx.x;
    int t0 = blockIdx.y * 64;
    int tid = threadIdx.x;
    __shared__ float invf[32];
    if (tid < 32) invf[tid] = (float)exp(-9.210340371976184 * (double)tid / 32.0);
    __syncthreads();

    int tok = tid >> 2;
    int quad = tid & 3;
    int e0 = quad * 16, f0 = quad * 8;
    int t = t0 + tok;

    const float* qrow = raw + (size_t)t * NRAW + h * 64 + e0;
    const float* krow = raw + (size_t)t * NRAW + 4096 + h * 64 + e0;
    float qv[16], kv[16];
#pragma unroll
    for (int i = 0; i < 4; ++i) {
        *reinterpret_cast<float4*>(qv + 4 * i) = *reinterpret_cast<const float4*>(qrow + 4 * i);
        *reinterpret_cast<float4*>(kv + 4 * i) = *reinterpret_cast<const float4*>(krow + 4 * i);
    }
    float* qo = Qo + ((size_t)h * T_TOK + t) * 64;
    float* ko = Ko + ((size_t)h * T_TOK + t) * 64;
    float tval = (float)t;
#pragma unroll
    for (int fl = 0; fl < 8; ++fl) {
        int f = f0 + fl;
        float ang = tval * invf[f];
        float cs = cosf(ang), sn = sinf(ang);
        float q1 = qv[2 * fl], q2 = qv[2 * fl + 1];
        float k1 = kv[2 * fl], k2 = kv[2 * fl + 1];
        qo[f]      = q1 * cs - q2 * sn;
        qo[f + 32] = q1 * sn + q2 * cs;
        ko[f]      = k1 * cs - k2 * sn;
        ko[f + 32] = k1 * sn + k2 * cs;
    }
}

// ---------------------------------------------------------------------------
// Block means -> block scores -> causal top-8 bitmask per (head, query block).
// ---------------------------------------------------------------------------
__global__ __launch_bounds__(256)
void blockstats_kernel(const float* __restrict__ Q, const float* __restrict__ K,
                       unsigned long long* __restrict__ maskbits)
{
    int h = blockIdx.x, tid = threadIdx.x;
    __shared__ float qm[64][64];
    __shared__ float kmT[64][64];
    __shared__ float sc[64][64];

    for (int idx = tid; idx < 4096; idx += 256) {
        int blk = idx >> 6, d = idx & 63;
        const float* Qp = Q + ((size_t)h * T_TOK + blk * 16) * 64 + d;
        const float* Kp = K + ((size_t)h * T_TOK + blk * 16) * 64 + d;
        float sq = 0.f, sk = 0.f;
#pragma unroll
        for (int l = 0; l < 16; ++l) { sq += Qp[l * 64]; sk += Kp[l * 64]; }
        qm[blk][d] = sq * 0.0625f;
        kmT[d][blk] = sk * 0.0625f;
    }
    __syncthreads();
    for (int idx = tid; idx < 4096; idx += 256) {
        int r = idx >> 6, c = idx & 63;
        float s = 0.f;
#pragma unroll
        for (int d = 0; d < 64; ++d) s += qm[r][d] * kmT[d][c];
        sc[r][c] = s;
    }
    __syncthreads();
    if (tid < 64) {
        int r = tid;
        unsigned long long bits = 0ull;
        int nsel = (r + 1 < 8) ? (r + 1) : 8;
        for (int sel = 0; sel < nsel; ++sel) {
            float best = -1e38f; int bi = 0;
            for (int kb = 0; kb <= r; ++kb) {
                float v = sc[r][kb];
                if (v > best) { best = v; bi = kb; }
            }
            sc[r][bi] = -1e38f;
            bits |= (1ull << bi);
        }
        maskbits[h * NB + r] = bits;
    }
}

// ---------------------------------------------------------------------------
// Sparse flash attention. CTA = (head, 16-query block), 256 threads.
// V comes from raw buffer rows (t, 8704), cols 8192 + (h%8)*64.
// ---------------------------------------------------------------------------
__global__ __launch_bounds__(256)
void attn_kernel(const float* __restrict__ Q, const float* __restrict__ K,
                 const float* __restrict__ Vraw, const unsigned long long* __restrict__ maskbits,
                 const float* __restrict__ sink_scalars, const float* __restrict__ v_nulls,
                 float* __restrict__ ctx)
{
    int h = blockIdx.x, qb = blockIdx.y;
    int tid = threadIdx.x;
    int qi = tid >> 4, kj = tid & 15;
    int s = h & 7;
    __shared__ float qs[16][68], ks[16][68];
    __shared__ float vs[16][64];
    __shared__ float ps[16][17];

    const float* Qh = Q + ((size_t)h * T_TOK + qb * 16) * 64;
    for (int i = tid; i < 1024; i += 256) qs[i >> 6][i & 63] = Qh[i];
    __syncthreads();

    unsigned long long bm = maskbits[h * NB + qb];
    float m = NEGBIG, l = 0.f;
    float a0 = 0.f, a1 = 0.f, a2 = 0.f, a3 = 0.f;
    int itok = qb * 16 + qi;

    for (int kb = 0; kb <= qb; ++kb) {
        bool blk_ok = ((bm >> kb) & 1ull) || (kb < 4) || (kb == qb);
        if (!blk_ok && kb != qb - 1) continue;

        const float* Kh = K + ((size_t)h * T_TOK + kb * 16) * 64;
        const float* Vh = Vraw + (size_t)(kb * 16) * NRAW + 8192 + s * 64;
        for (int i = tid; i < 1024; i += 256) ks[i >> 6][i & 63] = Kh[i];
        for (int i = tid; i < 1024; i += 256) vs[i >> 6][i & 63] = Vh[(size_t)(i >> 6) * NRAW + (i & 63)];
        __syncthreads();

        float scv = 0.f;
        {
            const float4* q4 = reinterpret_cast<const float4*>(qs[qi]);
            const float4* k4 = reinterpret_cast<const float4*>(ks[kj]);
#pragma unroll
            for (int d4 = 0; d4 < 16; ++d4) {
                float4 a = q4[d4], b = k4[d4];
                scv += a.x * b.x + a.y * b.y + a.z * b.z + a.w * b.w;
            }
        }
        scv *= 0.125f;

        int j = kb * 16 + kj;
        bool valid = (j <= itok) && (blk_ok || (j >= itok - 16));
        if (!valid) scv = NEGBIG;

        float mx = scv;
#pragma unroll
        for (int o = 8; o; o >>= 1) mx = fmaxf(mx, __shfl_xor_sync(0xffffffffu, mx, o, 16));
        float mn = fmaxf(m, mx);
        float alpha = __expf(m - mn);
        float p = __expf(scv - mn);
        float pr = p;
#pragma unroll
        for (int o = 8; o; o >>= 1) pr += __shfl_xor_sync(0xffffffffu, pr, o, 16);
        l = l * alpha + pr;
        m = mn;
        ps[qi][kj] = p;
        __syncthreads();

        a0 *= alpha; a1 *= alpha; a2 *= alpha; a3 *= alpha;
#pragma unroll
        for (int k2 = 0; k2 < 16; ++k2) {
            float pv = ps[qi][k2];
            float4 vv = *reinterpret_cast<const float4*>(&vs[k2][kj * 4]);
            a0 += pv * vv.x; a1 += pv * vv.y; a2 += pv * vv.z; a3 += pv * vv.w;
        }
        __syncthreads();
    }

    float sv = sink_scalars[h];
    float mn = fmaxf(m, sv);
    float alpha = __expf(m - mn);
    float pk = __expf(sv - mn);
    l = l * alpha + pk;
    float inv = 1.f / l;
    const float* vn = v_nulls + h * 64 + kj * 4;
    float* op = ctx + (size_t)itok * 4096 + h * 64 + kj * 4;
    op[0] = (a0 * alpha + pk * vn[0]) * inv;
    op[1] = (a1 * alpha + pk * vn[1]) * inv;
    op[2] = (a2 * alpha + pk * vn[2]) * inv;
    op[3] = (a3 * alpha + pk * vn[3]) * inv;
}

// ---------------------------------------------------------------------------
// split-K reduce + bias/8
// ---------------------------------------------------------------------------
__global__ void reduce_out(const float* __restrict__ part, const float* __restrict__ WOb,
                           float* __restrict__ out)
{
    int idx = blockIdx.x * 256 + threadIdx.x;
    int col = idx & 511;
    float b = 0.f;
#pragma unroll
    for (int n = 0; n < 8; ++n) b += WOb[n * 512 + col];
    const int S = T_TOK * 512;
    out[idx] = 0.125f * (part[idx] + part[S + idx] + part[2 * S + idx] + part[3 * S + idx] + b);
}

// ---------------------------------------------------------------------------
extern "C" void kernel_launch(void* const* d_in, const int* in_sizes, int n_in,
                              void* d_out, int out_size)
{
    const float* x   = (const float*)d_in[0];
    const float* WQ  = (const float*)d_in[1];
    const float* WK  = (const float*)d_in[2];
    const float* bK  = (const float*)d_in[3];
    const float* WV  = (const float*)d_in[4];
    const float* bV  = (const float*)d_in[5];
    const float* Am  = (const float*)d_in[6];
    const float* idb = (const float*)d_in[7];
    const float* snk = (const float*)d_in[8];
    const float* vnl = (const float*)d_in[9];
    const float* WO  = (const float*)d_in[10];
    const float* WOb = (const float*)d_in[11];
    float* out = (float*)d_out;

    float *weff, *biasv, *raw, *Qb, *Kb, *ctx, *part;
    unsigned long long* mb;
    cudaGetSymbolAddress((void**)&weff,  g_Weff);
    cudaGetSymbolAddress((void**)&biasv, g_bias);
    cudaGetSymbolAddress((void**)&raw,   g_raw);
    cudaGetSymbolAddress((void**)&Qb,    g_Q);
    cudaGetSymbolAddress((void**)&Kb,    g_K);
    cudaGetSymbolAddress((void**)&ctx,   g_ctx);
    cudaGetSymbolAddress((void**)&part,  g_part);
    cudaGetSymbolAddress((void**)&mb,    g_mask);

    prep_misc<<<1024, 256>>>(Am, idb, bK, bV, WV, weff, biasv);
    prep_fold<<<dim3(2, 64), 128>>>(Am, idb, WQ, WK, weff);

    // Q/K/V projection, 3xTF32 accurate
    mma_gemm<true, true, 1, true><<<dim3(68, 8, 1), 256>>>(x, weff, biasv, raw, 1024, NRAW, 512);

    rope_kernel<<<dim3(64, 16), 256>>>(raw, Qb, Kb);
    blockstats_kernel<<<64, 256>>>(Qb, Kb, mb);
    attn_kernel<<<dim3(64, 64), 256>>>(Qb, Kb, raw, mb, snk, vnl, ctx);

    // output projection, single tf32 (continuous path)
    mma_gemm<false, false, 4, false><<<dim3(4, 8, 4), 256>>>(ctx, WO, nullptr, part, 1024, 512, 4096);
    reduce_out<<<2048, 256>>>(part, WOb, out);
}

// round 6
// speedup vs baseline: 1.8761x; 1.1275x over previous
#include <cuda_runtime.h>
#include <cuda_bf16.h>
#include <cstdint>

// ---------------------------------------------------------------------------
// SSA attention, 3xTF32 pipeline, v6.
//  prep_misc : copy WK/WV rows into Weff tail + invf table
//  prep_fold : WQeff rows = per-head T_h^T @ WQ_blk   (3xTF32)
//  qkv_gemm  : raw = x @ [WQeff(4096) | WK(512) | WV(512)]^T  (3xTF32)
//              epilogue: Q region -> rope -> g_Q ; K/V regions -> +bias -> kraw/vraw
//  ktrans    : per-head K_all = kraw_s @ T_h (3xTF32) + rope -> g_K
//  blockstats: block means -> 64x64 scores -> causal top-8 bitmask
//  attn      : sparse flash attention (+sink), fp32
//  mma_gemm  : split-K=4 partials of ctx @ WO_flat (single tf32)
//  reduce_out: mean over splits + bias/8
// ---------------------------------------------------------------------------

#define T_TOK   1024
#define NB      64
#define NEGBIG  (-1e30f)
#define NPROJ   5120          // 4096 q + 512 k + 512 v

__device__ float g_Weff[NPROJ * 512];
__device__ float g_invf[32];
__device__ float g_kraw[T_TOK * 512];
__device__ float g_vraw[T_TOK * 512];
__device__ float g_Q[64 * T_TOK * 64];
__device__ float g_K[64 * T_TOK * 64];
__device__ float g_ctx[T_TOK * 4096];
__device__ float g_part[4 * T_TOK * 512];
__device__ unsigned long long g_mask[64 * NB];

__device__ __forceinline__ float tf32r(float x) {
    uint32_t u;
    asm("cvt.rna.tf32.f32 %0, %1;" : "=r"(u) : "f"(x));
    return __uint_as_float(u);
}

__device__ __forceinline__ void mma8(float* c, const uint32_t* a, const uint32_t* b) {
    asm volatile(
        "mma.sync.aligned.m16n8k8.row.col.f32.tf32.tf32.f32 "
        "{%0,%1,%2,%3}, {%4,%5,%6,%7}, {%8,%9}, {%0,%1,%2,%3};"
        : "+f"(c[0]), "+f"(c[1]), "+f"(c[2]), "+f"(c[3])
        : "r"(a[0]), "r"(a[1]), "r"(a[2]), "r"(a[3]), "r"(b[0]), "r"(b[1]));
}

// ---------------------------------------------------------------------------
// misc prep: WK/WV rows into Weff tail + invf table (fp64-accurate)
// ---------------------------------------------------------------------------
__global__ void prep_misc(const float* __restrict__ WK, const float* __restrict__ WV,
                          float* __restrict__ Weff)
{
    int idx = blockIdx.x * 256 + threadIdx.x;
    Weff[4096 * 512 + idx] = WK[idx];
    Weff[4608 * 512 + idx] = WV[idx];
    if (idx < 32) g_invf[idx] = (float)exp(-9.210340371976184 * (double)idx / 32.0);
}

// ---------------------------------------------------------------------------
// Q weight folding, 3xTF32: WQeff[e,c] = sum_d T_h[d,e] * WQ_h[d,c]
//   T_h = (A - A^T) + diag(1 + id_bias[h])
// grid (64 heads), 128 threads. smem 48KB exactly (validated in r5).
// ---------------------------------------------------------------------------
__global__ __launch_bounds__(128)
void prep_fold(const float* __restrict__ A, const float* __restrict__ idb,
               const float* __restrict__ WQ, float* __restrict__ Weff)
{
    int h = blockIdx.x;
    int tid = threadIdx.x;
    int warp = tid >> 5, lane = tid & 31;
    int g = lane >> 2, tg = lane & 3;
    __shared__ float Th[64][64], Tl[64][64];   // Tt[e][d] = T[d][e]
    __shared__ float Wh[64][32], Wl[64][32];

    for (int idx = tid; idx < 4096; idx += 128) {
        int e = idx >> 6, d = idx & 63;
        float v = A[d * 64 + e] - A[e * 64 + d];
        if (d == e) v += 1.f + idb[h * 64 + e];
        float hi = tf32r(v);
        Th[e][d] = hi;
        Tl[e][d] = tf32r(v - hi);
    }
    const float* Wsrc = WQ + (size_t)(h * 64) * 512;
    float* Wdst = Weff + (size_t)(h * 64) * 512;

    for (int chunk = 0; chunk < 16; ++chunk) {
        __syncthreads();
        for (int idx = tid; idx < 2048; idx += 128) {
            int d = idx >> 5, n = idx & 31;
            float v = Wsrc[(size_t)d * 512 + chunk * 32 + n];
            float hi = tf32r(v);
            Wh[d][n] = hi;
            Wl[d][n] = tf32r(v - hi);
        }
        __syncthreads();

        float c[4][4];
#pragma unroll
        for (int mt = 0; mt < 4; ++mt)
#pragma unroll
            for (int r = 0; r < 4; ++r) c[mt][r] = 0.f;

#pragma unroll
        for (int k0 = 0; k0 < 64; k0 += 8) {
            uint32_t ah[4][4], al[4][4], bh[2], bl[2];
#pragma unroll
            for (int mt = 0; mt < 4; ++mt) {
                int mb = mt * 16;
                ah[mt][0] = __float_as_uint(Th[mb + g][k0 + tg]);
                ah[mt][1] = __float_as_uint(Th[mb + g + 8][k0 + tg]);
                ah[mt][2] = __float_as_uint(Th[mb + g][k0 + tg + 4]);
                ah[mt][3] = __float_as_uint(Th[mb + g + 8][k0 + tg + 4]);
                al[mt][0] = __float_as_uint(Tl[mb + g][k0 + tg]);
                al[mt][1] = __float_as_uint(Tl[mb + g + 8][k0 + tg]);
                al[mt][2] = __float_as_uint(Tl[mb + g][k0 + tg + 4]);
                al[mt][3] = __float_as_uint(Tl[mb + g + 8][k0 + tg + 4]);
            }
            int nb = warp * 8;
            bh[0] = __float_as_uint(Wh[k0 + tg][nb + g]);
            bh[1] = __float_as_uint(Wh[k0 + tg + 4][nb + g]);
            bl[0] = __float_as_uint(Wl[k0 + tg][nb + g]);
            bl[1] = __float_as_uint(Wl[k0 + tg + 4][nb + g]);
#pragma unroll
            for (int mt = 0; mt < 4; ++mt) {
                mma8(c[mt], ah[mt], bh);
                mma8(c[mt], ah[mt], bl);
                mma8(c[mt], al[mt], bh);
            }
        }
#pragma unroll
        for (int mt = 0; mt < 4; ++mt) {
            int row = mt * 16 + g;
            int col = chunk * 32 + warp * 8 + 2 * tg;
            *reinterpret_cast<float2*>(Wdst + (size_t)row * 512 + col)
                = make_float2(c[mt][0], c[mt][1]);
            *reinterpret_cast<float2*>(Wdst + (size_t)(row + 8) * 512 + col)
                = make_float2(c[mt][2], c[mt][3]);
        }
    }
}

// ---------------------------------------------------------------------------
// QKV projection, 3xTF32, fused epilogue:
//   cols [0,4096)    : Q -> rope -> g_Q[h][t][d]
//   cols [4096,4608) : kraw = . + bK
//   cols [4608,5120) : vraw = . + bV
// 128x128 tile, 256 thr, 8 warps. Region uniform per CTA (boundaries 128-aligned).
// ---------------------------------------------------------------------------
__global__ __launch_bounds__(256)
void qkv_gemm(const float* __restrict__ Ag, const float* __restrict__ Bg,
              const float* __restrict__ bK, const float* __restrict__ bV,
              float* __restrict__ Qo, float* __restrict__ kraw, float* __restrict__ vraw)
{
    const int K = 512;
    __shared__ float Ah[16][132], Bh[16][132];
    __shared__ float Al[16][132], Bl[16][132];
    __shared__ float sInv[32];
    int tid = threadIdx.x;
    int warp = tid >> 5, lane = tid & 31;
    int wm = warp >> 2, wn = warp & 3;
    int g = lane >> 2, tg = lane & 3;
    int m0 = blockIdx.y * 128, n0 = blockIdx.x * 128;
    if (tid < 32) sInv[tid] = g_invf[tid];

    float c[4][4][4];
#pragma unroll
    for (int i = 0; i < 4; ++i)
#pragma unroll
        for (int j = 0; j < 4; ++j)
#pragma unroll
            for (int r = 0; r < 4; ++r) c[i][j][r] = 0.f;

    for (int k0 = 0; k0 < K; k0 += 16) {
#pragma unroll
        for (int q = 0; q < 2; ++q) {
            int idx = q * 256 + tid;
            int row = idx >> 2, kq = (idx & 3) << 2;
            float4 a = *reinterpret_cast<const float4*>(Ag + (size_t)(m0 + row) * K + k0 + kq);
            float h0 = tf32r(a.x), h1 = tf32r(a.y), h2 = tf32r(a.z), h3 = tf32r(a.w);
            Ah[kq + 0][row] = h0; Ah[kq + 1][row] = h1;
            Ah[kq + 2][row] = h2; Ah[kq + 3][row] = h3;
            Al[kq + 0][row] = tf32r(a.x - h0); Al[kq + 1][row] = tf32r(a.y - h1);
            Al[kq + 2][row] = tf32r(a.z - h2); Al[kq + 3][row] = tf32r(a.w - h3);
        }
#pragma unroll
        for (int q = 0; q < 2; ++q) {
            int idx = q * 256 + tid;
            int row = idx >> 2, kq = (idx & 3) << 2;
            float4 b = *reinterpret_cast<const float4*>(Bg + (size_t)(n0 + row) * K + k0 + kq);
            float h0 = tf32r(b.x), h1 = tf32r(b.y), h2 = tf32r(b.z), h3 = tf32r(b.w);
            Bh[kq + 0][row] = h0; Bh[kq + 1][row] = h1;
            Bh[kq + 2][row] = h2; Bh[kq + 3][row] = h3;
            Bl[kq + 0][row] = tf32r(b.x - h0); Bl[kq + 1][row] = tf32r(b.y - h1);
            Bl[kq + 2][row] = tf32r(b.z - h2); Bl[kq + 3][row] = tf32r(b.w - h3);
        }
        __syncthreads();
#pragma unroll
        for (int h8 = 0; h8 < 16; h8 += 8) {
            uint32_t afh[4][4], bfh[4][2];
            uint32_t afl[4][4], bfl[4][2];
#pragma unroll
            for (int mt = 0; mt < 4; ++mt) {
                int mb = wm * 64 + mt * 16;
                afh[mt][0] = __float_as_uint(Ah[h8 + tg][mb + g]);
                afh[mt][1] = __float_as_uint(Ah[h8 + tg][mb + g + 8]);
                afh[mt][2] = __float_as_uint(Ah[h8 + tg + 4][mb + g]);
                afh[mt][3] = __float_as_uint(Ah[h8 + tg + 4][mb + g + 8]);
                afl[mt][0] = __float_as_uint(Al[h8 + tg][mb + g]);
                afl[mt][1] = __float_as_uint(Al[h8 + tg][mb + g + 8]);
                afl[mt][2] = __float_as_uint(Al[h8 + tg + 4][mb + g]);
                afl[mt][3] = __float_as_uint(Al[h8 + tg + 4][mb + g + 8]);
            }
#pragma unroll
            for (int nt = 0; nt < 4; ++nt) {
                int nb = wn * 32 + nt * 8;
                bfh[nt][0] = __float_as_uint(Bh[h8 + tg][nb + g]);
                bfh[nt][1] = __float_as_uint(Bh[h8 + tg + 4][nb + g]);
                bfl[nt][0] = __float_as_uint(Bl[h8 + tg][nb + g]);
                bfl[nt][1] = __float_as_uint(Bl[h8 + tg + 4][nb + g]);
            }
#pragma unroll
            for (int mt = 0; mt < 4; ++mt)
#pragma unroll
                for (int nt = 0; nt < 4; ++nt) {
                    mma8(c[mt][nt], afh[mt], bfh[nt]);
                    mma8(c[mt][nt], afh[mt], bfl[nt]);
                    mma8(c[mt][nt], afl[mt], bfh[nt]);
                }
        }
        __syncthreads();
    }

#pragma unroll
    for (int mt = 0; mt < 4; ++mt) {
        int row = m0 + wm * 64 + mt * 16 + g;
#pragma unroll
        for (int nt = 0; nt < 4; ++nt) {
            int col = n0 + wn * 32 + nt * 8 + 2 * tg;
            float c0 = c[mt][nt][0], c1 = c[mt][nt][1];
            float c2 = c[mt][nt][2], c3 = c[mt][nt][3];
            if (n0 < 4096) {
                int h = col >> 6, f = (col & 63) >> 1;
                float iv = sInv[f];
                float sn0, cs0, sn1, cs1;
                sincosf((float)row * iv, &sn0, &cs0);
                sincosf((float)(row + 8) * iv, &sn1, &cs1);
                float* q0 = Qo + ((size_t)h * T_TOK + row) * 64;
                float* q1 = Qo + ((size_t)h * T_TOK + row + 8) * 64;
                q0[f]      = c0 * cs0 - c1 * sn0;
                q0[f + 32] = c0 * sn0 + c1 * cs0;
                q1[f]      = c2 * cs1 - c3 * sn1;
                q1[f + 32] = c2 * sn1 + c3 * cs1;
            } else if (n0 < 4608) {
                int cc = col - 4096;
                float b0 = bK[cc], b1 = bK[cc + 1];
                *reinterpret_cast<float2*>(kraw + (size_t)row * 512 + cc)
                    = make_float2(c0 + b0, c1 + b1);
                *reinterpret_cast<float2*>(kraw + (size_t)(row + 8) * 512 + cc)
                    = make_float2(c2 + b0, c3 + b1);
            } else {
                int cc = col - 4608;
                float b0 = bV[cc], b1 = bV[cc + 1];
                *reinterpret_cast<float2*>(vraw + (size_t)row * 512 + cc)
                    = make_float2(c0 + b0, c1 + b1);
                *reinterpret_cast<float2*>(vraw + (size_t)(row + 8) * 512 + cc)
                    = make_float2(c2 + b0, c3 + b1);
            }
        }
    }
}

// ---------------------------------------------------------------------------
// Per-head K transform + rope, 3xTF32:
//   K_all[h][t][e] = sum_d kraw[t][s*64+d] * T_h[d][e], then rope.
// grid (8 row-tiles, 64 heads), 256 thr (8 warps x 16 rows).
// ---------------------------------------------------------------------------
__global__ __launch_bounds__(256)
void ktrans_rope(const float* __restrict__ A, const float* __restrict__ idb,
                 const float* __restrict__ kraw, float* __restrict__ Ko)
{
    int rt = blockIdx.x, h = blockIdx.y;
    int s = h & 7;
    int tid = threadIdx.x;
    int warp = tid >> 5, lane = tid & 31;
    int g = lane >> 2, tg = lane & 3;
    __shared__ float Thh[64][64], Thl[64][64];   // [d][e]
    __shared__ float sInv[32];
    if (tid < 32) sInv[tid] = g_invf[tid];

    for (int idx = tid; idx < 4096; idx += 256) {
        int d = idx >> 6, e = idx & 63;
        float v = A[d * 64 + e] - A[e * 64 + d];
        if (d == e) v += 1.f + idb[h * 64 + e];
        float hi = tf32r(v);
        Thh[d][e] = hi;
        Thl[d][e] = tf32r(v - hi);
    }
    __syncthreads();

    int t0 = rt * 128 + warp * 16;
    const float* Ap = kraw + (size_t)t0 * 512 + s * 64;

    float c[8][4];
#pragma unroll
    for (int nt = 0; nt < 8; ++nt)
#pragma unroll
        for (int r = 0; r < 4; ++r) c[nt][r] = 0.f;

#pragma unroll
    for (int k0 = 0; k0 < 64; k0 += 8) {
        float a0 = Ap[(size_t)g * 512 + k0 + tg];
        float a1 = Ap[(size_t)(g + 8) * 512 + k0 + tg];
        float a2 = Ap[(size_t)g * 512 + k0 + tg + 4];
        float a3 = Ap[(size_t)(g + 8) * 512 + k0 + tg + 4];
        uint32_t ah[4], al[4];
        float h0 = tf32r(a0), h1 = tf32r(a1), h2 = tf32r(a2), h3 = tf32r(a3);
        ah[0] = __float_as_uint(h0); al[0] = __float_as_uint(tf32r(a0 - h0));
        ah[1] = __float_as_uint(h1); al[1] = __float_as_uint(tf32r(a1 - h1));
        ah[2] = __float_as_uint(h2); al[2] = __float_as_uint(tf32r(a2 - h2));
        ah[3] = __float_as_uint(h3); al[3] = __float_as_uint(tf32r(a3 - h3));
#pragma unroll
        for (int nt = 0; nt < 8; ++nt) {
            uint32_t bh[2], bl[2];
            int nb = nt * 8;
            bh[0] = __float_as_uint(Thh[k0 + tg][nb + g]);
            bh[1] = __float_as_uint(Thh[k0 + tg + 4][nb + g]);
            bl[0] = __float_as_uint(Thl[k0 + tg][nb + g]);
            bl[1] = __float_as_uint(Thl[k0 + tg + 4][nb + g]);
            mma8(c[nt], ah, bh);
            mma8(c[nt], ah, bl);
            mma8(c[nt], al, bh);
        }
    }

#pragma unroll
    for (int nt = 0; nt < 8; ++nt) {
        int col = nt * 8 + 2 * tg;
        int f = col >> 1;
        float iv = sInv[f];
        int ta = t0 + g, tb = t0 + g + 8;
        float sn0, cs0, sn1, cs1;
        sincosf((float)ta * iv, &sn0, &cs0);
        sincosf((float)tb * iv, &sn1, &cs1);
        float* k0p = Ko + ((size_t)h * T_TOK + ta) * 64;
        float* k1p = Ko + ((size_t)h * T_TOK + tb) * 64;
        k0p[f]      = c[nt][0] * cs0 - c[nt][1] * sn0;
        k0p[f + 32] = c[nt][0] * sn0 + c[nt][1] * cs0;
        k1p[f]      = c[nt][2] * cs1 - c[nt][3] * sn1;
        k1p[f + 32] = c[nt][2] * sn1 + c[nt][3] * cs1;
    }
}

// ---------------------------------------------------------------------------
// Generic tf32 mma GEMM (single tf32) for the output projection, split-K.
// B is (K x N) row-major.
// ---------------------------------------------------------------------------
template<int SPLITK>
__global__ __launch_bounds__(256)
void mma_gemm_nn(const float* __restrict__ Ag, const float* __restrict__ Bg,
                 float* __restrict__ Cg, int M, int N, int K)
{
    __shared__ float As[16][132];
    __shared__ float Bs[16][132];
    int tid = threadIdx.x;
    int warp = tid >> 5, lane = tid & 31;
    int wm = warp >> 2, wn = warp & 3;
    int g = lane >> 2, tg = lane & 3;
    int m0 = blockIdx.y * 128, n0 = blockIdx.x * 128;
    int kchunk = K / SPLITK;
    int kbeg = blockIdx.z * kchunk;
    int kend = kbeg + kchunk;

    float c[4][4][4];
#pragma unroll
    for (int i = 0; i < 4; ++i)
#pragma unroll
        for (int j = 0; j < 4; ++j)
#pragma unroll
            for (int r = 0; r < 4; ++r) c[i][j][r] = 0.f;

    for (int k0 = kbeg; k0 < kend; k0 += 16) {
#pragma unroll
        for (int q = 0; q < 2; ++q) {
            int idx = q * 256 + tid;
            int row = idx >> 2, kq = (idx & 3) << 2;
            float4 a = *reinterpret_cast<const float4*>(Ag + (size_t)(m0 + row) * K + k0 + kq);
            As[kq + 0][row] = tf32r(a.x); As[kq + 1][row] = tf32r(a.y);
            As[kq + 2][row] = tf32r(a.z); As[kq + 3][row] = tf32r(a.w);
        }
#pragma unroll
        for (int q = 0; q < 2; ++q) {
            int idx = q * 256 + tid;
            int r = idx >> 5, ccol = (idx & 31) << 2;
            float4 b = *reinterpret_cast<const float4*>(Bg + (size_t)(k0 + r) * N + n0 + ccol);
            Bs[r][ccol + 0] = tf32r(b.x); Bs[r][ccol + 1] = tf32r(b.y);
            Bs[r][ccol + 2] = tf32r(b.z); Bs[r][ccol + 3] = tf32r(b.w);
        }
        __syncthreads();
#pragma unroll
        for (int h8 = 0; h8 < 16; h8 += 8) {
            uint32_t af[4][4], bf[4][2];
#pragma unroll
            for (int mt = 0; mt < 4; ++mt) {
                int mb = wm * 64 + mt * 16;
                af[mt][0] = __float_as_uint(As[h8 + tg][mb + g]);
                af[mt][1] = __float_as_uint(As[h8 + tg][mb + g + 8]);
                af[mt][2] = __float_as_uint(As[h8 + tg + 4][mb + g]);
                af[mt][3] = __float_as_uint(As[h8 + tg + 4][mb + g + 8]);
            }
#pragma unroll
            for (int nt = 0; nt < 4; ++nt) {
                int nb = wn * 32 + nt * 8;
                bf[nt][0] = __float_as_uint(Bs[h8 + tg][nb + g]);
                bf[nt][1] = __float_as_uint(Bs[h8 + tg + 4][nb + g]);
            }
#pragma unroll
            for (int mt = 0; mt < 4; ++mt)
#pragma unroll
                for (int nt = 0; nt < 4; ++nt) mma8(c[mt][nt], af[mt], bf[nt]);
        }
        __syncthreads();
    }

    float* Cp = Cg + (size_t)blockIdx.z * M * N;
#pragma unroll
    for (int mt = 0; mt < 4; ++mt) {
        int row = m0 + wm * 64 + mt * 16 + g;
#pragma unroll
        for (int nt = 0; nt < 4; ++nt) {
            int col = n0 + wn * 32 + nt * 8 + 2 * tg;
            *reinterpret_cast<float2*>(Cp + (size_t)row * N + col)
                = make_float2(c[mt][nt][0], c[mt][nt][1]);
            *reinterpret_cast<float2*>(Cp + (size_t)(row + 8) * N + col)
                = make_float2(c[mt][nt][2], c[mt][nt][3]);
        }
    }
}

// ---------------------------------------------------------------------------
// Block means -> block scores -> causal top-8 bitmask per (head, query block).
// ---------------------------------------------------------------------------
__global__ __launch_bounds__(256)
void blockstats_kernel(const float* __restrict__ Q, const float* __restrict__ K,
                       unsigned long long* __restrict__ maskbits)
{
    int h = blockIdx.x, tid = threadIdx.x;
    __shared__ float qm[64][64];
    __shared__ float kmT[64][64];
    __shared__ float sc[64][64];

    for (int idx = tid; idx < 4096; idx += 256) {
        int blk = idx >> 6, d = idx & 63;
        const float* Qp = Q + ((size_t)h * T_TOK + blk * 16) * 64 + d;
        const float* Kp = K + ((size_t)h * T_TOK + blk * 16) * 64 + d;
        float sq = 0.f, sk = 0.f;
#pragma unroll
        for (int l = 0; l < 16; ++l) { sq += Qp[l * 64]; sk += Kp[l * 64]; }
        qm[blk][d] = sq * 0.0625f;
        kmT[d][blk] = sk * 0.0625f;
    }
    __syncthreads();
    for (int idx = tid; idx < 4096; idx += 256) {
        int r = idx >> 6, c = idx & 63;
        float s = 0.f;
#pragma unroll
        for (int d = 0; d < 64; ++d) s += qm[r][d] * kmT[d][c];
        sc[r][c] = s;
    }
    __syncthreads();
    if (tid < 64) {
        int r = tid;
        unsigned long long bits = 0ull;
        int nsel = (r + 1 < 8) ? (r + 1) : 8;
        for (int sel = 0; sel < nsel; ++sel) {
            float best = -1e38f; int bi = 0;
            for (int kb = 0; kb <= r; ++kb) {
                float v = sc[r][kb];
                if (v > best) { best = v; bi = kb; }
            }
            sc[r][bi] = -1e38f;
            bits |= (1ull << bi);
        }
        maskbits[h * NB + r] = bits;
    }
}

// ---------------------------------------------------------------------------
// Sparse flash attention. CTA = (head, 16-query block), 256 threads.
// V from vraw rows (t, 512), cols (h%8)*64.
// ---------------------------------------------------------------------------
__global__ __launch_bounds__(256)
void attn_kernel(const float* __restrict__ Q, const float* __restrict__ K,
                 const float* __restrict__ Vraw, const unsigned long long* __restrict__ maskbits,
                 const float* __restrict__ sink_scalars, const float* __restrict__ v_nulls,
                 float* __restrict__ ctx)
{
    int h = blockIdx.x, qb = blockIdx.y;
    int tid = threadIdx.x;
    int qi = tid >> 4, kj = tid & 15;
    int s = h & 7;
    __shared__ float qs[16][68], ks[16][68];
    __shared__ float vs[16][64];
    __shared__ float ps[16][17];

    const float* Qh = Q + ((size_t)h * T_TOK + qb * 16) * 64;
    for (int i = tid; i < 1024; i += 256) qs[i >> 6][i & 63] = Qh[i];
    __syncthreads();

    unsigned long long bm = maskbits[h * NB + qb];
    float m = NEGBIG, l = 0.f;
    float a0 = 0.f, a1 = 0.f, a2 = 0.f, a3 = 0.f;
    int itok = qb * 16 + qi;

    for (int kb = 0; kb <= qb; ++kb) {
        bool blk_ok = ((bm >> kb) & 1ull) || (kb < 4) || (kb == qb);
        if (!blk_ok && kb != qb - 1) continue;

        const float* Kh = K + ((size_t)h * T_TOK + kb * 16) * 64;
        const float* Vh = Vraw + (size_t)(kb * 16) * 512 + s * 64;
        for (int i = tid; i < 1024; i += 256) ks[i >> 6][i & 63] = Kh[i];
        for (int i = tid; i < 1024; i += 256) vs[i >> 6][i & 63] = Vh[(size_t)(i >> 6) * 512 + (i & 63)];
        __syncthreads();

        float scv = 0.f;
        {
            const float4* q4 = reinterpret_cast<const float4*>(qs[qi]);
            const float4* k4 = reinterpret_cast<const float4*>(ks[kj]);
#pragma unroll
            for (int d4 = 0; d4 < 16; ++d4) {
                float4 a = q4[d4], b = k4[d4];
                scv += a.x * b.x + a.y * b.y + a.z * b.z + a.w * b.w;
            }
        }
        scv *= 0.125f;

        int j = kb * 16 + kj;
        bool valid = (j <= itok) && (blk_ok || (j >= itok - 16));
        if (!valid) scv = NEGBIG;

        float mx = scv;
#pragma unroll
        for (int o = 8; o; o >>= 1) mx = fmaxf(mx, __shfl_xor_sync(0xffffffffu, mx, o, 16));
        float mn = fmaxf(m, mx);
        float alpha = __expf(m - mn);
        float p = __expf(scv - mn);
        float pr = p;
#pragma unroll
        for (int o = 8; o; o >>= 1) pr += __shfl_xor_sync(0xffffffffu, pr, o, 16);
        l = l * alpha + pr;
        m = mn;
        ps[qi][kj] = p;
        __syncthreads();

        a0 *= alpha; a1 *= alpha; a2 *= alpha; a3 *= alpha;
#pragma unroll
        for (int k2 = 0; k2 < 16; ++k2) {
            float pv = ps[qi][k2];
            float4 vv = *reinterpret_cast<const float4*>(&vs[k2][kj * 4]);
            a0 += pv * vv.x; a1 += pv * vv.y; a2 += pv * vv.z; a3 += pv * vv.w;
        }
        __syncthreads();
    }

    float sv = sink_scalars[h];
    float mn = fmaxf(m, sv);
    float alpha = __expf(m - mn);
    float pk = __expf(sv - mn);
    l = l * alpha + pk;
    float inv = 1.f / l;
    const float* vn = v_nulls + h * 64 + kj * 4;
    float* op = ctx + (size_t)itok * 4096 + h * 64 + kj * 4;
    op[0] = (a0 * alpha + pk * vn[0]) * inv;
    op[1] = (a1 * alpha + pk * vn[1]) * inv;
    op[2] = (a2 * alpha + pk * vn[2]) * inv;
    op[3] = (a3 * alpha + pk * vn[3]) * inv;
}

// ---------------------------------------------------------------------------
// split-K reduce + bias/8
// ---------------------------------------------------------------------------
__global__ void reduce_out(const float* __restrict__ part, const float* __restrict__ WOb,
                           float* __restrict__ out)
{
    int idx = blockIdx.x * 256 + threadIdx.x;
    int col = idx & 511;
    float b = 0.f;
#pragma unroll
    for (int n = 0; n < 8; ++n) b += WOb[n * 512 + col];
    const int S = T_TOK * 512;
    out[idx] = 0.125f * (part[idx] + part[S + idx] + part[2 * S + idx] + part[3 * S + idx] + b);
}

// ---------------------------------------------------------------------------
extern "C" void kernel_launch(void* const* d_in, const int* in_sizes, int n_in,
                              void* d_out, int out_size)
{
    const float* x   = (const float*)d_in[0];
    const float* WQ  = (const float*)d_in[1];
    const float* WK  = (const float*)d_in[2];
    const float* bK  = (const float*)d_in[3];
    const float* WV  = (const float*)d_in[4];
    const float* bV  = (const float*)d_in[5];
    const float* Am  = (const float*)d_in[6];
    const float* idb = (const float*)d_in[7];
    const float* snk = (const float*)d_in[8];
    const float* vnl = (const float*)d_in[9];
    const float* WO  = (const float*)d_in[10];
    const float* WOb = (const float*)d_in[11];
    float* out = (float*)d_out;

    float *weff, *kraw, *vraw, *Qb, *Kb, *ctx, *part;
    unsigned long long* mb;
    cudaGetSymbolAddress((void**)&weff, g_Weff);
    cudaGetSymbolAddress((void**)&kraw, g_kraw);
    cudaGetSymbolAddress((void**)&vraw, g_vraw);
    cudaGetSymbolAddress((void**)&Qb,   g_Q);
    cudaGetSymbolAddress((void**)&Kb,   g_K);
    cudaGetSymbolAddress((void**)&ctx,  g_ctx);
    cudaGetSymbolAddress((void**)&part, g_part);
    cudaGetSymbolAddress((void**)&mb,   g_mask);

    prep_misc<<<1024, 256>>>(WK, WV, weff);
    prep_fold<<<64, 128>>>(Am, idb, WQ, weff);

    qkv_gemm<<<dim3(40, 8), 256>>>(x, weff, bK, bV, Qb, kraw, vraw);
    ktrans_rope<<<dim3(8, 64), 256>>>(Am, idb, kraw, Kb);

    blockstats_kernel<<<64, 256>>>(Qb, Kb, mb);
    attn_kernel<<<dim3(64, 64), 256>>>(Qb, Kb, vraw, mb, snk, vnl, ctx);

    mma_gemm_nn<4><<<dim3(4, 8, 4), 256>>>(ctx, WO, part, 1024, 512, 4096);
    reduce_out<<<2048, 256>>>(part, WOb, out);
}

// round 7
// speedup vs baseline: 2.5167x; 1.3414x over previous
#include <cuda_runtime.h>
#include <cuda_bf16.h>
#include <cstdint>

// ---------------------------------------------------------------------------
// SSA attention, 3xTF32 pipeline, v7: attention moved to tensor cores.
//  prep_misc : copy WK/WV rows into Weff tail + invf table
//  prep_fold : WQeff rows = per-head T_h^T @ WQ_blk   (3xTF32)
//  qkv_gemm  : raw = x @ [WQeff|WK|WV]^T (3xTF32), epilogue ropes Q, biases K/V
//  ktrans    : per-head K = kraw_s @ T_h (3xTF32) + rope
//  blockstats: block means -> 64x64 scores -> causal top-8 bitmask
//  attn_mma  : warp-per-(h,qb) sparse flash attention, QK^T & PV in 3xTF32 mma
//  mma_gemm  : split-K=4 partials of ctx @ WO_flat (single tf32)
//  reduce_out: mean over splits + bias/8
// ---------------------------------------------------------------------------

#define T_TOK   1024
#define NB      64
#define NEGBIG  (-1e30f)
#define NPROJ   5120          // 4096 q + 512 k + 512 v

__device__ float g_Weff[NPROJ * 512];
__device__ float g_invf[32];
__device__ float g_kraw[T_TOK * 512];
__device__ float g_vraw[T_TOK * 512];
__device__ float g_Q[64 * T_TOK * 64];
__device__ float g_K[64 * T_TOK * 64];
__device__ float g_ctx[T_TOK * 4096];
__device__ float g_part[4 * T_TOK * 512];
__device__ unsigned long long g_mask[64 * NB];

__device__ __forceinline__ float tf32r(float x) {
    uint32_t u;
    asm("cvt.rna.tf32.f32 %0, %1;" : "=r"(u) : "f"(x));
    return __uint_as_float(u);
}

__device__ __forceinline__ void mma8(float* c, const uint32_t* a, const uint32_t* b) {
    asm volatile(
        "mma.sync.aligned.m16n8k8.row.col.f32.tf32.tf32.f32 "
        "{%0,%1,%2,%3}, {%4,%5,%6,%7}, {%8,%9}, {%0,%1,%2,%3};"
        : "+f"(c[0]), "+f"(c[1]), "+f"(c[2]), "+f"(c[3])
        : "r"(a[0]), "r"(a[1]), "r"(a[2]), "r"(a[3]), "r"(b[0]), "r"(b[1]));
}

// ---------------------------------------------------------------------------
__global__ void prep_misc(const float* __restrict__ WK, const float* __restrict__ WV,
                          float* __restrict__ Weff)
{
    int idx = blockIdx.x * 256 + threadIdx.x;
    Weff[4096 * 512 + idx] = WK[idx];
    Weff[4608 * 512 + idx] = WV[idx];
    if (idx < 32) g_invf[idx] = (float)exp(-9.210340371976184 * (double)idx / 32.0);
}

// ---------------------------------------------------------------------------
// Q weight folding, 3xTF32 (validated r5/r6).
// ---------------------------------------------------------------------------
__global__ __launch_bounds__(128)
void prep_fold(const float* __restrict__ A, const float* __restrict__ idb,
               const float* __restrict__ WQ, float* __restrict__ Weff)
{
    int h = blockIdx.x;
    int tid = threadIdx.x;
    int warp = tid >> 5, lane = tid & 31;
    int g = lane >> 2, tg = lane & 3;
    __shared__ float Th[64][64], Tl[64][64];
    __shared__ float Wh[64][32], Wl[64][32];

    for (int idx = tid; idx < 4096; idx += 128) {
        int e = idx >> 6, d = idx & 63;
        float v = A[d * 64 + e] - A[e * 64 + d];
        if (d == e) v += 1.f + idb[h * 64 + e];
        float hi = tf32r(v);
        Th[e][d] = hi;
        Tl[e][d] = tf32r(v - hi);
    }
    const float* Wsrc = WQ + (size_t)(h * 64) * 512;
    float* Wdst = Weff + (size_t)(h * 64) * 512;

    for (int chunk = 0; chunk < 16; ++chunk) {
        __syncthreads();
        for (int idx = tid; idx < 2048; idx += 128) {
            int d = idx >> 5, n = idx & 31;
            float v = Wsrc[(size_t)d * 512 + chunk * 32 + n];
            float hi = tf32r(v);
            Wh[d][n] = hi;
            Wl[d][n] = tf32r(v - hi);
        }
        __syncthreads();

        float c[4][4];
#pragma unroll
        for (int mt = 0; mt < 4; ++mt)
#pragma unroll
            for (int r = 0; r < 4; ++r) c[mt][r] = 0.f;

#pragma unroll
        for (int k0 = 0; k0 < 64; k0 += 8) {
            uint32_t ah[4][4], al[4][4], bh[2], bl[2];
#pragma unroll
            for (int mt = 0; mt < 4; ++mt) {
                int mb = mt * 16;
                ah[mt][0] = __float_as_uint(Th[mb + g][k0 + tg]);
                ah[mt][1] = __float_as_uint(Th[mb + g + 8][k0 + tg]);
                ah[mt][2] = __float_as_uint(Th[mb + g][k0 + tg + 4]);
                ah[mt][3] = __float_as_uint(Th[mb + g + 8][k0 + tg + 4]);
                al[mt][0] = __float_as_uint(Tl[mb + g][k0 + tg]);
                al[mt][1] = __float_as_uint(Tl[mb + g + 8][k0 + tg]);
                al[mt][2] = __float_as_uint(Tl[mb + g][k0 + tg + 4]);
                al[mt][3] = __float_as_uint(Tl[mb + g + 8][k0 + tg + 4]);
            }
            int nb = warp * 8;
            bh[0] = __float_as_uint(Wh[k0 + tg][nb + g]);
            bh[1] = __float_as_uint(Wh[k0 + tg + 4][nb + g]);
            bl[0] = __float_as_uint(Wl[k0 + tg][nb + g]);
            bl[1] = __float_as_uint(Wl[k0 + tg + 4][nb + g]);
#pragma unroll
            for (int mt = 0; mt < 4; ++mt) {
                mma8(c[mt], ah[mt], bh);
                mma8(c[mt], ah[mt], bl);
                mma8(c[mt], al[mt], bh);
            }
        }
#pragma unroll
        for (int mt = 0; mt < 4; ++mt) {
            int row = mt * 16 + g;
            int col = chunk * 32 + warp * 8 + 2 * tg;
            *reinterpret_cast<float2*>(Wdst + (size_t)row * 512 + col)
                = make_float2(c[mt][0], c[mt][1]);
            *reinterpret_cast<float2*>(Wdst + (size_t)(row + 8) * 512 + col)
                = make_float2(c[mt][2], c[mt][3]);
        }
    }
}

// ---------------------------------------------------------------------------
// QKV projection, 3xTF32, fused rope/bias epilogue (validated r6).
// ---------------------------------------------------------------------------
__global__ __launch_bounds__(256)
void qkv_gemm(const float* __restrict__ Ag, const float* __restrict__ Bg,
              const float* __restrict__ bK, const float* __restrict__ bV,
              float* __restrict__ Qo, float* __restrict__ kraw, float* __restrict__ vraw)
{
    const int K = 512;
    __shared__ float Ah[16][132], Bh[16][132];
    __shared__ float Al[16][132], Bl[16][132];
    __shared__ float sInv[32];
    int tid = threadIdx.x;
    int warp = tid >> 5, lane = tid & 31;
    int wm = warp >> 2, wn = warp & 3;
    int g = lane >> 2, tg = lane & 3;
    int m0 = blockIdx.y * 128, n0 = blockIdx.x * 128;
    if (tid < 32) sInv[tid] = g_invf[tid];

    float c[4][4][4];
#pragma unroll
    for (int i = 0; i < 4; ++i)
#pragma unroll
        for (int j = 0; j < 4; ++j)
#pragma unroll
            for (int r = 0; r < 4; ++r) c[i][j][r] = 0.f;

    for (int k0 = 0; k0 < K; k0 += 16) {
#pragma unroll
        for (int q = 0; q < 2; ++q) {
            int idx = q * 256 + tid;
            int row = idx >> 2, kq = (idx & 3) << 2;
            float4 a = *reinterpret_cast<const float4*>(Ag + (size_t)(m0 + row) * K + k0 + kq);
            float h0 = tf32r(a.x), h1 = tf32r(a.y), h2 = tf32r(a.z), h3 = tf32r(a.w);
            Ah[kq + 0][row] = h0; Ah[kq + 1][row] = h1;
            Ah[kq + 2][row] = h2; Ah[kq + 3][row] = h3;
            Al[kq + 0][row] = tf32r(a.x - h0); Al[kq + 1][row] = tf32r(a.y - h1);
            Al[kq + 2][row] = tf32r(a.z - h2); Al[kq + 3][row] = tf32r(a.w - h3);
        }
#pragma unroll
        for (int q = 0; q < 2; ++q) {
            int idx = q * 256 + tid;
            int row = idx >> 2, kq = (idx & 3) << 2;
            float4 b = *reinterpret_cast<const float4*>(Bg + (size_t)(n0 + row) * K + k0 + kq);
            float h0 = tf32r(b.x), h1 = tf32r(b.y), h2 = tf32r(b.z), h3 = tf32r(b.w);
            Bh[kq + 0][row] = h0; Bh[kq + 1][row] = h1;
            Bh[kq + 2][row] = h2; Bh[kq + 3][row] = h3;
            Bl[kq + 0][row] = tf32r(b.x - h0); Bl[kq + 1][row] = tf32r(b.y - h1);
            Bl[kq + 2][row] = tf32r(b.z - h2); Bl[kq + 3][row] = tf32r(b.w - h3);
        }
        __syncthreads();
#pragma unroll
        for (int h8 = 0; h8 < 16; h8 += 8) {
            uint32_t afh[4][4], bfh[4][2];
            uint32_t afl[4][4], bfl[4][2];
#pragma unroll
            for (int mt = 0; mt < 4; ++mt) {
                int mb = wm * 64 + mt * 16;
                afh[mt][0] = __float_as_uint(Ah[h8 + tg][mb + g]);
                afh[mt][1] = __float_as_uint(Ah[h8 + tg][mb + g + 8]);
                afh[mt][2] = __float_as_uint(Ah[h8 + tg + 4][mb + g]);
                afh[mt][3] = __float_as_uint(Ah[h8 + tg + 4][mb + g + 8]);
                afl[mt][0] = __float_as_uint(Al[h8 + tg][mb + g]);
                afl[mt][1] = __float_as_uint(Al[h8 + tg][mb + g + 8]);
                afl[mt][2] = __float_as_uint(Al[h8 + tg + 4][mb + g]);
                afl[mt][3] = __float_as_uint(Al[h8 + tg + 4][mb + g + 8]);
            }
#pragma unroll
            for (int nt = 0; nt < 4; ++nt) {
                int nb = wn * 32 + nt * 8;
                bfh[nt][0] = __float_as_uint(Bh[h8 + tg][nb + g]);
                bfh[nt][1] = __float_as_uint(Bh[h8 + tg + 4][nb + g]);
                bfl[nt][0] = __float_as_uint(Bl[h8 + tg][nb + g]);
                bfl[nt][1] = __float_as_uint(Bl[h8 + tg + 4][nb + g]);
            }
#pragma unroll
            for (int mt = 0; mt < 4; ++mt)
#pragma unroll
                for (int nt = 0; nt < 4; ++nt) {
                    mma8(c[mt][nt], afh[mt], bfh[nt]);
                    mma8(c[mt][nt], afh[mt], bfl[nt]);
                    mma8(c[mt][nt], afl[mt], bfh[nt]);
                }
        }
        __syncthreads();
    }

#pragma unroll
    for (int mt = 0; mt < 4; ++mt) {
        int row = m0 + wm * 64 + mt * 16 + g;
#pragma unroll
        for (int nt = 0; nt < 4; ++nt) {
            int col = n0 + wn * 32 + nt * 8 + 2 * tg;
            float c0 = c[mt][nt][0], c1 = c[mt][nt][1];
            float c2 = c[mt][nt][2], c3 = c[mt][nt][3];
            if (n0 < 4096) {
                int h = col >> 6, f = (col & 63) >> 1;
                float iv = sInv[f];
                float sn0, cs0, sn1, cs1;
                sincosf((float)row * iv, &sn0, &cs0);
                sincosf((float)(row + 8) * iv, &sn1, &cs1);
                float* q0 = Qo + ((size_t)h * T_TOK + row) * 64;
                float* q1 = Qo + ((size_t)h * T_TOK + row + 8) * 64;
                q0[f]      = c0 * cs0 - c1 * sn0;
                q0[f + 32] = c0 * sn0 + c1 * cs0;
                q1[f]      = c2 * cs1 - c3 * sn1;
                q1[f + 32] = c2 * sn1 + c3 * cs1;
            } else if (n0 < 4608) {
                int cc = col - 4096;
                float b0 = bK[cc], b1 = bK[cc + 1];
                *reinterpret_cast<float2*>(kraw + (size_t)row * 512 + cc)
                    = make_float2(c0 + b0, c1 + b1);
                *reinterpret_cast<float2*>(kraw + (size_t)(row + 8) * 512 + cc)
                    = make_float2(c2 + b0, c3 + b1);
            } else {
                int cc = col - 4608;
                float b0 = bV[cc], b1 = bV[cc + 1];
                *reinterpret_cast<float2*>(vraw + (size_t)row * 512 + cc)
                    = make_float2(c0 + b0, c1 + b1);
                *reinterpret_cast<float2*>(vraw + (size_t)(row + 8) * 512 + cc)
                    = make_float2(c2 + b0, c3 + b1);
            }
        }
    }
}

// ---------------------------------------------------------------------------
// Per-head K transform + rope, 3xTF32 (validated r6).
// ---------------------------------------------------------------------------
__global__ __launch_bounds__(256)
void ktrans_rope(const float* __restrict__ A, const float* __restrict__ idb,
                 const float* __restrict__ kraw, float* __restrict__ Ko)
{
    int rt = blockIdx.x, h = blockIdx.y;
    int s = h & 7;
    int tid = threadIdx.x;
    int warp = tid >> 5, lane = tid & 31;
    int g = lane >> 2, tg = lane & 3;
    __shared__ float Thh[64][64], Thl[64][64];
    __shared__ float sInv[32];
    if (tid < 32) sInv[tid] = g_invf[tid];

    for (int idx = tid; idx < 4096; idx += 256) {
        int d = idx >> 6, e = idx & 63;
        float v = A[d * 64 + e] - A[e * 64 + d];
        if (d == e) v += 1.f + idb[h * 64 + e];
        float hi = tf32r(v);
        Thh[d][e] = hi;
        Thl[d][e] = tf32r(v - hi);
    }
    __syncthreads();

    int t0 = rt * 128 + warp * 16;
    const float* Ap = kraw + (size_t)t0 * 512 + s * 64;

    float c[8][4];
#pragma unroll
    for (int nt = 0; nt < 8; ++nt)
#pragma unroll
        for (int r = 0; r < 4; ++r) c[nt][r] = 0.f;

#pragma unroll
    for (int k0 = 0; k0 < 64; k0 += 8) {
        float a0 = Ap[(size_t)g * 512 + k0 + tg];
        float a1 = Ap[(size_t)(g + 8) * 512 + k0 + tg];
        float a2 = Ap[(size_t)g * 512 + k0 + tg + 4];
        float a3 = Ap[(size_t)(g + 8) * 512 + k0 + tg + 4];
        uint32_t ah[4], al[4];
        float h0 = tf32r(a0), h1 = tf32r(a1), h2 = tf32r(a2), h3 = tf32r(a3);
        ah[0] = __float_as_uint(h0); al[0] = __float_as_uint(tf32r(a0 - h0));
        ah[1] = __float_as_uint(h1); al[1] = __float_as_uint(tf32r(a1 - h1));
        ah[2] = __float_as_uint(h2); al[2] = __float_as_uint(tf32r(a2 - h2));
        ah[3] = __float_as_uint(h3); al[3] = __float_as_uint(tf32r(a3 - h3));
#pragma unroll
        for (int nt = 0; nt < 8; ++nt) {
            uint32_t bh[2], bl[2];
            int nb = nt * 8;
            bh[0] = __float_as_uint(Thh[k0 + tg][nb + g]);
            bh[1] = __float_as_uint(Thh[k0 + tg + 4][nb + g]);
            bl[0] = __float_as_uint(Thl[k0 + tg][nb + g]);
            bl[1] = __float_as_uint(Thl[k0 + tg + 4][nb + g]);
            mma8(c[nt], ah, bh);
            mma8(c[nt], ah, bl);
            mma8(c[nt], al, bh);
        }
    }

#pragma unroll
    for (int nt = 0; nt < 8; ++nt) {
        int col = nt * 8 + 2 * tg;
        int f = col >> 1;
        float iv = sInv[f];
        int ta = t0 + g, tb = t0 + g + 8;
        float sn0, cs0, sn1, cs1;
        sincosf((float)ta * iv, &sn0, &cs0);
        sincosf((float)tb * iv, &sn1, &cs1);
        float* k0p = Ko + ((size_t)h * T_TOK + ta) * 64;
        float* k1p = Ko + ((size_t)h * T_TOK + tb) * 64;
        k0p[f]      = c[nt][0] * cs0 - c[nt][1] * sn0;
        k0p[f + 32] = c[nt][0] * sn0 + c[nt][1] * cs0;
        k1p[f]      = c[nt][2] * cs1 - c[nt][3] * sn1;
        k1p[f + 32] = c[nt][2] * sn1 + c[nt][3] * cs1;
    }
}

// ---------------------------------------------------------------------------
// Output projection, single tf32, split-K (validated r6).
// ---------------------------------------------------------------------------
template<int SPLITK>
__global__ __launch_bounds__(256)
void mma_gemm_nn(const float* __restrict__ Ag, const float* __restrict__ Bg,
                 float* __restrict__ Cg, int M, int N, int K)
{
    __shared__ float As[16][132];
    __shared__ float Bs[16][132];
    int tid = threadIdx.x;
    int warp = tid >> 5, lane = tid & 31;
    int wm = warp >> 2, wn = warp & 3;
    int g = lane >> 2, tg = lane & 3;
    int m0 = blockIdx.y * 128, n0 = blockIdx.x * 128;
    int kchunk = K / SPLITK;
    int kbeg = blockIdx.z * kchunk;
    int kend = kbeg + kchunk;

    float c[4][4][4];
#pragma unroll
    for (int i = 0; i < 4; ++i)
#pragma unroll
        for (int j = 0; j < 4; ++j)
#pragma unroll
            for (int r = 0; r < 4; ++r) c[i][j][r] = 0.f;

    for (int k0 = kbeg; k0 < kend; k0 += 16) {
#pragma unroll
        for (int q = 0; q < 2; ++q) {
            int idx = q * 256 + tid;
            int row = idx >> 2, kq = (idx & 3) << 2;
            float4 a = *reinterpret_cast<const float4*>(Ag + (size_t)(m0 + row) * K + k0 + kq);
            As[kq + 0][row] = tf32r(a.x); As[kq + 1][row] = tf32r(a.y);
            As[kq + 2][row] = tf32r(a.z); As[kq + 3][row] = tf32r(a.w);
        }
#pragma unroll
        for (int q = 0; q < 2; ++q) {
            int idx = q * 256 + tid;
            int r = idx >> 5, ccol = (idx & 31) << 2;
            float4 b = *reinterpret_cast<const float4*>(Bg + (size_t)(k0 + r) * N + n0 + ccol);
            Bs[r][ccol + 0] = tf32r(b.x); Bs[r][ccol + 1] = tf32r(b.y);
            Bs[r][ccol + 2] = tf32r(b.z); Bs[r][ccol + 3] = tf32r(b.w);
        }
        __syncthreads();
#pragma unroll
        for (int h8 = 0; h8 < 16; h8 += 8) {
            uint32_t af[4][4], bf[4][2];
#pragma unroll
            for (int mt = 0; mt < 4; ++mt) {
                int mb = wm * 64 + mt * 16;
                af[mt][0] = __float_as_uint(As[h8 + tg][mb + g]);
                af[mt][1] = __float_as_uint(As[h8 + tg][mb + g + 8]);
                af[mt][2] = __float_as_uint(As[h8 + tg + 4][mb + g]);
                af[mt][3] = __float_as_uint(As[h8 + tg + 4][mb + g + 8]);
            }
#pragma unroll
            for (int nt = 0; nt < 4; ++nt) {
                int nb = wn * 32 + nt * 8;
                bf[nt][0] = __float_as_uint(Bs[h8 + tg][nb + g]);
                bf[nt][1] = __float_as_uint(Bs[h8 + tg + 4][nb + g]);
            }
#pragma unroll
            for (int mt = 0; mt < 4; ++mt)
#pragma unroll
                for (int nt = 0; nt < 4; ++nt) mma8(c[mt][nt], af[mt], bf[nt]);
        }
        __syncthreads();
    }

    float* Cp = Cg + (size_t)blockIdx.z * M * N;
#pragma unroll
    for (int mt = 0; mt < 4; ++mt) {
        int row = m0 + wm * 64 + mt * 16 + g;
#pragma unroll
        for (int nt = 0; nt < 4; ++nt) {
            int col = n0 + wn * 32 + nt * 8 + 2 * tg;
            *reinterpret_cast<float2*>(Cp + (size_t)row * N + col)
                = make_float2(c[mt][nt][0], c[mt][nt][1]);
            *reinterpret_cast<float2*>(Cp + (size_t)(row + 8) * N + col)
                = make_float2(c[mt][nt][2], c[mt][nt][3]);
        }
    }
}

// ---------------------------------------------------------------------------
// Block means -> block scores -> causal top-8 bitmask (validated r5/r6).
// ---------------------------------------------------------------------------
__global__ __launch_bounds__(256)
void blockstats_kernel(const float* __restrict__ Q, const float* __restrict__ K,
                       unsigned long long* __restrict__ maskbits)
{
    int h = blockIdx.x, tid = threadIdx.x;
    __shared__ float qm[64][64];
    __shared__ float kmT[64][64];
    __shared__ float sc[64][64];

    for (int idx = tid; idx < 4096; idx += 256) {
        int blk = idx >> 6, d = idx & 63;
        const float* Qp = Q + ((size_t)h * T_TOK + blk * 16) * 64 + d;
        const float* Kp = K + ((size_t)h * T_TOK + blk * 16) * 64 + d;
        float sq = 0.f, sk = 0.f;
#pragma unroll
        for (int l = 0; l < 16; ++l) { sq += Qp[l * 64]; sk += Kp[l * 64]; }
        qm[blk][d] = sq * 0.0625f;
        kmT[d][blk] = sk * 0.0625f;
    }
    __syncthreads();
    for (int idx = tid; idx < 4096; idx += 256) {
        int r = idx >> 6, c = idx & 63;
        float s = 0.f;
#pragma unroll
        for (int d = 0; d < 64; ++d) s += qm[r][d] * kmT[d][c];
        sc[r][c] = s;
    }
    __syncthreads();
    if (tid < 64) {
        int r = tid;
        unsigned long long bits = 0ull;
        int nsel = (r + 1 < 8) ? (r + 1) : 8;
        for (int sel = 0; sel < nsel; ++sel) {
            float best = -1e38f; int bi = 0;
            for (int kb = 0; kb <= r; ++kb) {
                float v = sc[r][kb];
                if (v > best) { best = v; bi = kb; }
            }
            sc[r][bi] = -1e38f;
            bits |= (1ull << bi);
        }
        maskbits[h * NB + r] = bits;
    }
}

// ---------------------------------------------------------------------------
// Sparse flash attention, tensor-core version. One WARP per (head, qb).
// Q(16x64) in registers as 3xTF32 a-frags. Per visited block:
//   S = Q@K^T (3xTF32 mma), mask+scale, online softmax in c-frag layout
//   (rows g,g+8 live in lane-quads; quad shfl reduces), P through per-warp
//   smem to a-frag layout, ctx += P@V (3xTF32 mma). Sink folded at the end.
// ---------------------------------------------------------------------------
__global__ __launch_bounds__(128)
void attn_mma(const float* __restrict__ Q, const float* __restrict__ K,
              const float* __restrict__ Vraw, const unsigned long long* __restrict__ maskbits,
              const float* __restrict__ sink_scalars, const float* __restrict__ v_nulls,
              float* __restrict__ ctx)
{
    int warp = threadIdx.x >> 5, lane = threadIdx.x & 31;
    int g = lane >> 2, tg = lane & 3;
    int idx = blockIdx.x * 4 + warp;
    int h = idx >> 6, qb = idx & 63;
    int s = h & 7;
    __shared__ float psm[4][16][20];

    // Q a-fragments, hi/lo
    uint32_t qh[8][4], ql[8][4];
    {
        const float* Qp = Q + ((size_t)h * T_TOK + qb * 16) * 64;
#pragma unroll
        for (int ks = 0; ks < 8; ++ks) {
            float a0 = Qp[g * 64 + ks * 8 + tg];
            float a1 = Qp[(g + 8) * 64 + ks * 8 + tg];
            float a2 = Qp[g * 64 + ks * 8 + tg + 4];
            float a3 = Qp[(g + 8) * 64 + ks * 8 + tg + 4];
            float h0 = tf32r(a0), h1 = tf32r(a1), h2 = tf32r(a2), h3 = tf32r(a3);
            qh[ks][0] = __float_as_uint(h0); ql[ks][0] = __float_as_uint(tf32r(a0 - h0));
            qh[ks][1] = __float_as_uint(h1); ql[ks][1] = __float_as_uint(tf32r(a1 - h1));
            qh[ks][2] = __float_as_uint(h2); ql[ks][2] = __float_as_uint(tf32r(a2 - h2));
            qh[ks][3] = __float_as_uint(h3); ql[ks][3] = __float_as_uint(tf32r(a3 - h3));
        }
    }

    float c[8][4];
#pragma unroll
    for (int nt = 0; nt < 8; ++nt)
#pragma unroll
        for (int r = 0; r < 4; ++r) c[nt][r] = 0.f;

    float m0 = NEGBIG, m1 = NEGBIG, l0 = 0.f, l1 = 0.f;
    unsigned long long bm = maskbits[h * NB + qb];
    int i0 = qb * 16 + g, i1 = i0 + 8;

    for (int kb = 0; kb <= qb; ++kb) {
        bool blk_ok = ((bm >> kb) & 1ull) || (kb < 4) || (kb == qb);
        if (!blk_ok && kb != qb - 1) continue;

        // S = Q @ K^T  (16x16), 3xTF32
        float sc[2][4];
#pragma unroll
        for (int nt = 0; nt < 2; ++nt)
#pragma unroll
            for (int r = 0; r < 4; ++r) sc[nt][r] = 0.f;

        const float* Kp = K + ((size_t)h * T_TOK + kb * 16) * 64;
#pragma unroll
        for (int ks = 0; ks < 8; ++ks) {
#pragma unroll
            for (int nt = 0; nt < 2; ++nt) {
                float b0f = Kp[(nt * 8 + g) * 64 + ks * 8 + tg];
                float b1f = Kp[(nt * 8 + g) * 64 + ks * 8 + tg + 4];
                float bh0 = tf32r(b0f), bh1 = tf32r(b1f);
                uint32_t bh[2] = { __float_as_uint(bh0), __float_as_uint(bh1) };
                uint32_t bl[2] = { __float_as_uint(tf32r(b0f - bh0)),
                                   __float_as_uint(tf32r(b1f - bh1)) };
                mma8(sc[nt], qh[ks], bh);
                mma8(sc[nt], qh[ks], bl);
                mma8(sc[nt], ql[ks], bh);
            }
        }

        // scale + mask (col j = kb*16 + nt*8 + 2tg + (r&1); row = g or g+8)
#pragma unroll
        for (int nt = 0; nt < 2; ++nt)
#pragma unroll
            for (int r = 0; r < 4; ++r) {
                int j = kb * 16 + nt * 8 + 2 * tg + (r & 1);
                int i = (r < 2) ? i0 : i1;
                float v = sc[nt][r] * 0.125f;
                bool valid = (j <= i) && (blk_ok || (j >= i - 16));
                sc[nt][r] = valid ? v : NEGBIG;
            }

        // online softmax (quad reduce across tg lanes)
        float mx0 = fmaxf(fmaxf(sc[0][0], sc[0][1]), fmaxf(sc[1][0], sc[1][1]));
        float mx1 = fmaxf(fmaxf(sc[0][2], sc[0][3]), fmaxf(sc[1][2], sc[1][3]));
        mx0 = fmaxf(mx0, __shfl_xor_sync(0xffffffffu, mx0, 1));
        mx0 = fmaxf(mx0, __shfl_xor_sync(0xffffffffu, mx0, 2));
        mx1 = fmaxf(mx1, __shfl_xor_sync(0xffffffffu, mx1, 1));
        mx1 = fmaxf(mx1, __shfl_xor_sync(0xffffffffu, mx1, 2));
        float mn0 = fmaxf(m0, mx0), mn1 = fmaxf(m1, mx1);
        float al0 = __expf(m0 - mn0), al1 = __expf(m1 - mn1);
        m0 = mn0; m1 = mn1;

        float p[2][4];
#pragma unroll
        for (int nt = 0; nt < 2; ++nt) {
            p[nt][0] = __expf(sc[nt][0] - mn0);
            p[nt][1] = __expf(sc[nt][1] - mn0);
            p[nt][2] = __expf(sc[nt][2] - mn1);
            p[nt][3] = __expf(sc[nt][3] - mn1);
        }
        float s0 = p[0][0] + p[0][1] + p[1][0] + p[1][1];
        float s1 = p[0][2] + p[0][3] + p[1][2] + p[1][3];
        s0 += __shfl_xor_sync(0xffffffffu, s0, 1);
        s0 += __shfl_xor_sync(0xffffffffu, s0, 2);
        s1 += __shfl_xor_sync(0xffffffffu, s1, 1);
        s1 += __shfl_xor_sync(0xffffffffu, s1, 2);
        l0 = l0 * al0 + s0;
        l1 = l1 * al1 + s1;

        // rescale ctx accumulators
#pragma unroll
        for (int nt = 0; nt < 8; ++nt) {
            c[nt][0] *= al0; c[nt][1] *= al0;
            c[nt][2] *= al1; c[nt][3] *= al1;
        }

        // P -> a-frag layout via per-warp smem
        __syncwarp();
#pragma unroll
        for (int nt = 0; nt < 2; ++nt) {
            psm[warp][g][nt * 8 + 2 * tg]         = p[nt][0];
            psm[warp][g][nt * 8 + 2 * tg + 1]     = p[nt][1];
            psm[warp][g + 8][nt * 8 + 2 * tg]     = p[nt][2];
            psm[warp][g + 8][nt * 8 + 2 * tg + 1] = p[nt][3];
        }
        __syncwarp();
        uint32_t pah[2][4], pal[2][4];
#pragma unroll
        for (int ks = 0; ks < 2; ++ks) {
            float a0 = psm[warp][g][ks * 8 + tg];
            float a1 = psm[warp][g + 8][ks * 8 + tg];
            float a2 = psm[warp][g][ks * 8 + tg + 4];
            float a3 = psm[warp][g + 8][ks * 8 + tg + 4];
            float h0 = tf32r(a0), h1 = tf32r(a1), h2 = tf32r(a2), h3 = tf32r(a3);
            pah[ks][0] = __float_as_uint(h0); pal[ks][0] = __float_as_uint(tf32r(a0 - h0));
            pah[ks][1] = __float_as_uint(h1); pal[ks][1] = __float_as_uint(tf32r(a1 - h1));
            pah[ks][2] = __float_as_uint(h2); pal[ks][2] = __float_as_uint(tf32r(a2 - h2));
            pah[ks][3] = __float_as_uint(h3); pal[ks][3] = __float_as_uint(tf32r(a3 - h3));
        }

        // ctx += P @ V  (16x64), 3xTF32
        const float* Vp = Vraw + (size_t)(kb * 16) * 512 + s * 64;
#pragma unroll
        for (int nt = 0; nt < 8; ++nt) {
#pragma unroll
            for (int ks = 0; ks < 2; ++ks) {
                float b0f = Vp[(size_t)(ks * 8 + tg) * 512 + nt * 8 + g];
                float b1f = Vp[(size_t)(ks * 8 + tg + 4) * 512 + nt * 8 + g];
                float bh0 = tf32r(b0f), bh1 = tf32r(b1f);
                uint32_t bh[2] = { __float_as_uint(bh0), __float_as_uint(bh1) };
                uint32_t bl[2] = { __float_as_uint(tf32r(b0f - bh0)),
                                   __float_as_uint(tf32r(b1f - bh1)) };
                mma8(c[nt], pah[ks], bh);
                mma8(c[nt], pah[ks], bl);
                mma8(c[nt], pal[ks], bh);
            }
        }
    }

    // sink + normalize + writeout
    float sv = sink_scalars[h];
    float fn0 = fmaxf(m0, sv), fn1 = fmaxf(m1, sv);
    float fa0 = __expf(m0 - fn0), fa1 = __expf(m1 - fn1);
    float pk0 = __expf(sv - fn0), pk1 = __expf(sv - fn1);
    float inv0 = 1.f / (l0 * fa0 + pk0);
    float inv1 = 1.f / (l1 * fa1 + pk1);
    const float* vn = v_nulls + h * 64;
#pragma unroll
    for (int nt = 0; nt < 8; ++nt) {
        int col = nt * 8 + 2 * tg;
        float vn0 = vn[col], vn1 = vn[col + 1];
        float* op0 = ctx + (size_t)(qb * 16 + g) * 4096 + h * 64 + col;
        float* op1 = ctx + (size_t)(qb * 16 + g + 8) * 4096 + h * 64 + col;
        *reinterpret_cast<float2*>(op0) =
            make_float2((c[nt][0] * fa0 + pk0 * vn0) * inv0,
                        (c[nt][1] * fa0 + pk0 * vn1) * inv0);
        *reinterpret_cast<float2*>(op1) =
            make_float2((c[nt][2] * fa1 + pk1 * vn0) * inv1,
                        (c[nt][3] * fa1 + pk1 * vn1) * inv1);
    }
}

// ---------------------------------------------------------------------------
__global__ void reduce_out(const float* __restrict__ part, const float* __restrict__ WOb,
                           float* __restrict__ out)
{
    int idx = blockIdx.x * 256 + threadIdx.x;
    int col = idx & 511;
    float b = 0.f;
#pragma unroll
    for (int n = 0; n < 8; ++n) b += WOb[n * 512 + col];
    const int S = T_TOK * 512;
    out[idx] = 0.125f * (part[idx] + part[S + idx] + part[2 * S + idx] + part[3 * S + idx] + b);
}

// ---------------------------------------------------------------------------
extern "C" void kernel_launch(void* const* d_in, const int* in_sizes, int n_in,
                              void* d_out, int out_size)
{
    const float* x   = (const float*)d_in[0];
    const float* WQ  = (const float*)d_in[1];
    const float* WK  = (const float*)d_in[2];
    const float* bK  = (const float*)d_in[3];
    const float* WV  = (const float*)d_in[4];
    const float* bV  = (const float*)d_in[5];
    const float* Am  = (const float*)d_in[6];
    const float* idb = (const float*)d_in[7];
    const float* snk = (const float*)d_in[8];
    const float* vnl = (const float*)d_in[9];
    const float* WO  = (const float*)d_in[10];
    const float* WOb = (const float*)d_in[11];
    float* out = (float*)d_out;

    float *weff, *kraw, *vraw, *Qb, *Kb, *ctx, *part;
    unsigned long long* mb;
    cudaGetSymbolAddress((void**)&weff, g_Weff);
    cudaGetSymbolAddress((void**)&kraw, g_kraw);
    cudaGetSymbolAddress((void**)&vraw, g_vraw);
    cudaGetSymbolAddress((void**)&Qb,   g_Q);
    cudaGetSymbolAddress((void**)&Kb,   g_K);
    cudaGetSymbolAddress((void**)&ctx,  g_ctx);
    cudaGetSymbolAddress((void**)&part, g_part);
    cudaGetSymbolAddress((void**)&mb,   g_mask);

    prep_misc<<<1024, 256>>>(WK, WV, weff);
    prep_fold<<<64, 128>>>(Am, idb, WQ, weff);

    qkv_gemm<<<dim3(40, 8), 256>>>(x, weff, bK, bV, Qb, kraw, vraw);
    ktrans_rope<<<dim3(8, 64), 256>>>(Am, idb, kraw, Kb);

    blockstats_kernel<<<64, 256>>>(Qb, Kb, mb);
    attn_mma<<<1024, 128>>>(Qb, Kb, vraw, mb, snk, vnl, ctx);

    mma_gemm_nn<4><<<dim3(4, 8, 4), 256>>>(ctx, WO, part, 1024, 512, 4096);
    reduce_out<<<2048, 256>>>(part, WOb, out);
}

// round 8
// speedup vs baseline: 2.7270x; 1.0836x over previous
#include <cuda_runtime.h>
#include <cuda_bf16.h>
#include <cstdint>

// ---------------------------------------------------------------------------
// SSA attention, 3xTF32 pipeline, v8.
//  v8: qkv_gemm register-prefetch pipelining; attn_mma K/V smem staging;
//      prep_fold split over 4 chunk-groups. Rest identical to validated v7.
// ---------------------------------------------------------------------------

#define T_TOK   1024
#define NB      64
#define NEGBIG  (-1e30f)
#define NPROJ   5120          // 4096 q + 512 k + 512 v

__device__ float g_Weff[NPROJ * 512];
__device__ float g_invf[32];
__device__ float g_kraw[T_TOK * 512];
__device__ float g_vraw[T_TOK * 512];
__device__ float g_Q[64 * T_TOK * 64];
__device__ float g_K[64 * T_TOK * 64];
__device__ float g_ctx[T_TOK * 4096];
__device__ float g_part[4 * T_TOK * 512];
__device__ unsigned long long g_mask[64 * NB];

__device__ __forceinline__ float tf32r(float x) {
    uint32_t u;
    asm("cvt.rna.tf32.f32 %0, %1;" : "=r"(u) : "f"(x));
    return __uint_as_float(u);
}

__device__ __forceinline__ void mma8(float* c, const uint32_t* a, const uint32_t* b) {
    asm volatile(
        "mma.sync.aligned.m16n8k8.row.col.f32.tf32.tf32.f32 "
        "{%0,%1,%2,%3}, {%4,%5,%6,%7}, {%8,%9}, {%0,%1,%2,%3};"
        : "+f"(c[0]), "+f"(c[1]), "+f"(c[2]), "+f"(c[3])
        : "r"(a[0]), "r"(a[1]), "r"(a[2]), "r"(a[3]), "r"(b[0]), "r"(b[1]));
}

// ---------------------------------------------------------------------------
__global__ void prep_misc(const float* __restrict__ WK, const float* __restrict__ WV,
                          float* __restrict__ Weff)
{
    int idx = blockIdx.x * 256 + threadIdx.x;
    Weff[4096 * 512 + idx] = WK[idx];
    Weff[4608 * 512 + idx] = WV[idx];
    if (idx < 32) g_invf[idx] = (float)exp(-9.210340371976184 * (double)idx / 32.0);
}

// ---------------------------------------------------------------------------
// Q weight folding, 3xTF32. grid (64 heads, 4 chunk-groups), 128 thr.
// ---------------------------------------------------------------------------
__global__ __launch_bounds__(128)
void prep_fold(const float* __restrict__ A, const float* __restrict__ idb,
               const float* __restrict__ WQ, float* __restrict__ Weff)
{
    int h = blockIdx.x, cg = blockIdx.y;
    int tid = threadIdx.x;
    int warp = tid >> 5, lane = tid & 31;
    int g = lane >> 2, tg = lane & 3;
    __shared__ float Th[64][64], Tl[64][64];
    __shared__ float Wh[64][32], Wl[64][32];

    for (int idx = tid; idx < 4096; idx += 128) {
        int e = idx >> 6, d = idx & 63;
        float v = A[d * 64 + e] - A[e * 64 + d];
        if (d == e) v += 1.f + idb[h * 64 + e];
        float hi = tf32r(v);
        Th[e][d] = hi;
        Tl[e][d] = tf32r(v - hi);
    }
    const float* Wsrc = WQ + (size_t)(h * 64) * 512;
    float* Wdst = Weff + (size_t)(h * 64) * 512;

    for (int chunk = cg * 4; chunk < cg * 4 + 4; ++chunk) {
        __syncthreads();
        for (int idx = tid; idx < 2048; idx += 128) {
            int d = idx >> 5, n = idx & 31;
            float v = Wsrc[(size_t)d * 512 + chunk * 32 + n];
            float hi = tf32r(v);
            Wh[d][n] = hi;
            Wl[d][n] = tf32r(v - hi);
        }
        __syncthreads();

        float c[4][4];
#pragma unroll
        for (int mt = 0; mt < 4; ++mt)
#pragma unroll
            for (int r = 0; r < 4; ++r) c[mt][r] = 0.f;

#pragma unroll
        for (int k0 = 0; k0 < 64; k0 += 8) {
            uint32_t ah[4][4], al[4][4], bh[2], bl[2];
#pragma unroll
            for (int mt = 0; mt < 4; ++mt) {
                int mb = mt * 16;
                ah[mt][0] = __float_as_uint(Th[mb + g][k0 + tg]);
                ah[mt][1] = __float_as_uint(Th[mb + g + 8][k0 + tg]);
                ah[mt][2] = __float_as_uint(Th[mb + g][k0 + tg + 4]);
                ah[mt][3] = __float_as_uint(Th[mb + g + 8][k0 + tg + 4]);
                al[mt][0] = __float_as_uint(Tl[mb + g][k0 + tg]);
                al[mt][1] = __float_as_uint(Tl[mb + g + 8][k0 + tg]);
                al[mt][2] = __float_as_uint(Tl[mb + g][k0 + tg + 4]);
                al[mt][3] = __float_as_uint(Tl[mb + g + 8][k0 + tg + 4]);
            }
            int nb = warp * 8;
            bh[0] = __float_as_uint(Wh[k0 + tg][nb + g]);
            bh[1] = __float_as_uint(Wh[k0 + tg + 4][nb + g]);
            bl[0] = __float_as_uint(Wl[k0 + tg][nb + g]);
            bl[1] = __float_as_uint(Wl[k0 + tg + 4][nb + g]);
#pragma unroll
            for (int mt = 0; mt < 4; ++mt) {
                mma8(c[mt], ah[mt], bh);
                mma8(c[mt], ah[mt], bl);
                mma8(c[mt], al[mt], bh);
            }
        }
#pragma unroll
        for (int mt = 0; mt < 4; ++mt) {
            int row = mt * 16 + g;
            int col = chunk * 32 + warp * 8 + 2 * tg;
            *reinterpret_cast<float2*>(Wdst + (size_t)row * 512 + col)
                = make_float2(c[mt][0], c[mt][1]);
            *reinterpret_cast<float2*>(Wdst + (size_t)(row + 8) * 512 + col)
                = make_float2(c[mt][2], c[mt][3]);
        }
    }
}

// ---------------------------------------------------------------------------
// QKV projection, 3xTF32, register-prefetch double buffering,
// fused rope/bias epilogue.
// ---------------------------------------------------------------------------
__global__ __launch_bounds__(256)
void qkv_gemm(const float* __restrict__ Ag, const float* __restrict__ Bg,
              const float* __restrict__ bK, const float* __restrict__ bV,
              float* __restrict__ Qo, float* __restrict__ kraw, float* __restrict__ vraw)
{
    const int K = 512;
    __shared__ float Ah[16][132], Bh[16][132];
    __shared__ float Al[16][132], Bl[16][132];
    __shared__ float sInv[32];
    int tid = threadIdx.x;
    int warp = tid >> 5, lane = tid & 31;
    int wm = warp >> 2, wn = warp & 3;
    int g = lane >> 2, tg = lane & 3;
    int m0 = blockIdx.y * 128, n0 = blockIdx.x * 128;
    if (tid < 32) sInv[tid] = g_invf[tid];

    // per-thread load coordinates (q = 0,1)
    int rowA[2], kqA[2];
#pragma unroll
    for (int q = 0; q < 2; ++q) {
        int idx = q * 256 + tid;
        rowA[q] = idx >> 2;
        kqA[q]  = (idx & 3) << 2;
    }

    float c[4][4][4];
#pragma unroll
    for (int i = 0; i < 4; ++i)
#pragma unroll
        for (int j = 0; j < 4; ++j)
#pragma unroll
            for (int r = 0; r < 4; ++r) c[i][j][r] = 0.f;

    float4 pa[2], pb[2];
#pragma unroll
    for (int q = 0; q < 2; ++q) {
        pa[q] = *reinterpret_cast<const float4*>(Ag + (size_t)(m0 + rowA[q]) * K + kqA[q]);
        pb[q] = *reinterpret_cast<const float4*>(Bg + (size_t)(n0 + rowA[q]) * K + kqA[q]);
    }

    for (int k0 = 0; k0 < K; k0 += 16) {
        // store prefetched tile with hi/lo split
#pragma unroll
        for (int q = 0; q < 2; ++q) {
            int row = rowA[q], kq = kqA[q];
            float4 a = pa[q];
            float h0 = tf32r(a.x), h1 = tf32r(a.y), h2 = tf32r(a.z), h3 = tf32r(a.w);
            Ah[kq + 0][row] = h0; Ah[kq + 1][row] = h1;
            Ah[kq + 2][row] = h2; Ah[kq + 3][row] = h3;
            Al[kq + 0][row] = tf32r(a.x - h0); Al[kq + 1][row] = tf32r(a.y - h1);
            Al[kq + 2][row] = tf32r(a.z - h2); Al[kq + 3][row] = tf32r(a.w - h3);
            float4 b = pb[q];
            float i0 = tf32r(b.x), i1 = tf32r(b.y), i2 = tf32r(b.z), i3 = tf32r(b.w);
            Bh[kq + 0][row] = i0; Bh[kq + 1][row] = i1;
            Bh[kq + 2][row] = i2; Bh[kq + 3][row] = i3;
            Bl[kq + 0][row] = tf32r(b.x - i0); Bl[kq + 1][row] = tf32r(b.y - i1);
            Bl[kq + 2][row] = tf32r(b.z - i2); Bl[kq + 3][row] = tf32r(b.w - i3);
        }
        __syncthreads();

        // issue next prefetch before compute (latency overlap)
        if (k0 + 16 < K) {
#pragma unroll
            for (int q = 0; q < 2; ++q) {
                pa[q] = *reinterpret_cast<const float4*>(
                    Ag + (size_t)(m0 + rowA[q]) * K + k0 + 16 + kqA[q]);
                pb[q] = *reinterpret_cast<const float4*>(
                    Bg + (size_t)(n0 + rowA[q]) * K + k0 + 16 + kqA[q]);
            }
        }

#pragma unroll
        for (int h8 = 0; h8 < 16; h8 += 8) {
            uint32_t afh[4][4], bfh[4][2];
            uint32_t afl[4][4], bfl[4][2];
#pragma unroll
            for (int mt = 0; mt < 4; ++mt) {
                int mb = wm * 64 + mt * 16;
                afh[mt][0] = __float_as_uint(Ah[h8 + tg][mb + g]);
                afh[mt][1] = __float_as_uint(Ah[h8 + tg][mb + g + 8]);
                afh[mt][2] = __float_as_uint(Ah[h8 + tg + 4][mb + g]);
                afh[mt][3] = __float_as_uint(Ah[h8 + tg + 4][mb + g + 8]);
                afl[mt][0] = __float_as_uint(Al[h8 + tg][mb + g]);
                afl[mt][1] = __float_as_uint(Al[h8 + tg][mb + g + 8]);
                afl[mt][2] = __float_as_uint(Al[h8 + tg + 4][mb + g]);
                afl[mt][3] = __float_as_uint(Al[h8 + tg + 4][mb + g + 8]);
            }
#pragma unroll
            for (int nt = 0; nt < 4; ++nt) {
                int nb = wn * 32 + nt * 8;
                bfh[nt][0] = __float_as_uint(Bh[h8 + tg][nb + g]);
                bfh[nt][1] = __float_as_uint(Bh[h8 + tg + 4][nb + g]);
                bfl[nt][0] = __float_as_uint(Bl[h8 + tg][nb + g]);
                bfl[nt][1] = __float_as_uint(Bl[h8 + tg + 4][nb + g]);
            }
#pragma unroll
            for (int mt = 0; mt < 4; ++mt)
#pragma unroll
                for (int nt = 0; nt < 4; ++nt) {
                    mma8(c[mt][nt], afh[mt], bfh[nt]);
                    mma8(c[mt][nt], afh[mt], bfl[nt]);
                    mma8(c[mt][nt], afl[mt], bfh[nt]);
                }
        }
        __syncthreads();
    }

#pragma unroll
    for (int mt = 0; mt < 4; ++mt) {
        int row = m0 + wm * 64 + mt * 16 + g;
#pragma unroll
        for (int nt = 0; nt < 4; ++nt) {
            int col = n0 + wn * 32 + nt * 8 + 2 * tg;
            float c0 = c[mt][nt][0], c1 = c[mt][nt][1];
            float c2 = c[mt][nt][2], c3 = c[mt][nt][3];
            if (n0 < 4096) {
                int h = col >> 6, f = (col & 63) >> 1;
                float iv = sInv[f];
                float sn0, cs0, sn1, cs1;
                sincosf((float)row * iv, &sn0, &cs0);
                sincosf((float)(row + 8) * iv, &sn1, &cs1);
                float* q0 = Qo + ((size_t)h * T_TOK + row) * 64;
                float* q1 = Qo + ((size_t)h * T_TOK + row + 8) * 64;
                q0[f]      = c0 * cs0 - c1 * sn0;
                q0[f + 32] = c0 * sn0 + c1 * cs0;
                q1[f]      = c2 * cs1 - c3 * sn1;
                q1[f + 32] = c2 * sn1 + c3 * cs1;
            } else if (n0 < 4608) {
                int cc = col - 4096;
                float b0 = bK[cc], b1 = bK[cc + 1];
                *reinterpret_cast<float2*>(kraw + (size_t)row * 512 + cc)
                    = make_float2(c0 + b0, c1 + b1);
                *reinterpret_cast<float2*>(kraw + (size_t)(row + 8) * 512 + cc)
                    = make_float2(c2 + b0, c3 + b1);
            } else {
                int cc = col - 4608;
                float b0 = bV[cc], b1 = bV[cc + 1];
                *reinterpret_cast<float2*>(vraw + (size_t)row * 512 + cc)
                    = make_float2(c0 + b0, c1 + b1);
                *reinterpret_cast<float2*>(vraw + (size_t)(row + 8) * 512 + cc)
                    = make_float2(c2 + b0, c3 + b1);
            }
        }
    }
}

// ---------------------------------------------------------------------------
// Per-head K transform + rope, 3xTF32 (validated r6/r7).
// ---------------------------------------------------------------------------
__global__ __launch_bounds__(256)
void ktrans_rope(const float* __restrict__ A, const float* __restrict__ idb,
                 const float* __restrict__ kraw, float* __restrict__ Ko)
{
    int rt = blockIdx.x, h = blockIdx.y;
    int s = h & 7;
    int tid = threadIdx.x;
    int warp = tid >> 5, lane = tid & 31;
    int g = lane >> 2, tg = lane & 3;
    __shared__ float Thh[64][64], Thl[64][64];
    __shared__ float sInv[32];
    if (tid < 32) sInv[tid] = g_invf[tid];

    for (int idx = tid; idx < 4096; idx += 256) {
        int d = idx >> 6, e = idx & 63;
        float v = A[d * 64 + e] - A[e * 64 + d];
        if (d == e) v += 1.f + idb[h * 64 + e];
        float hi = tf32r(v);
        Thh[d][e] = hi;
        Thl[d][e] = tf32r(v - hi);
    }
    __syncthreads();

    int t0 = rt * 128 + warp * 16;
    const float* Ap = kraw + (size_t)t0 * 512 + s * 64;

    float c[8][4];
#pragma unroll
    for (int nt = 0; nt < 8; ++nt)
#pragma unroll
        for (int r = 0; r < 4; ++r) c[nt][r] = 0.f;

#pragma unroll
    for (int k0 = 0; k0 < 64; k0 += 8) {
        float a0 = Ap[(size_t)g * 512 + k0 + tg];
        float a1 = Ap[(size_t)(g + 8) * 512 + k0 + tg];
        float a2 = Ap[(size_t)g * 512 + k0 + tg + 4];
        float a3 = Ap[(size_t)(g + 8) * 512 + k0 + tg + 4];
        uint32_t ah[4], al[4];
        float h0 = tf32r(a0), h1 = tf32r(a1), h2 = tf32r(a2), h3 = tf32r(a3);
        ah[0] = __float_as_uint(h0); al[0] = __float_as_uint(tf32r(a0 - h0));
        ah[1] = __float_as_uint(h1); al[1] = __float_as_uint(tf32r(a1 - h1));
        ah[2] = __float_as_uint(h2); al[2] = __float_as_uint(tf32r(a2 - h2));
        ah[3] = __float_as_uint(h3); al[3] = __float_as_uint(tf32r(a3 - h3));
#pragma unroll
        for (int nt = 0; nt < 8; ++nt) {
            uint32_t bh[2], bl[2];
            int nb = nt * 8;
            bh[0] = __float_as_uint(Thh[k0 + tg][nb + g]);
            bh[1] = __float_as_uint(Thh[k0 + tg + 4][nb + g]);
            bl[0] = __float_as_uint(Thl[k0 + tg][nb + g]);
            bl[1] = __float_as_uint(Thl[k0 + tg + 4][nb + g]);
            mma8(c[nt], ah, bh);
            mma8(c[nt], ah, bl);
            mma8(c[nt], al, bh);
        }
    }

#pragma unroll
    for (int nt = 0; nt < 8; ++nt) {
        int col = nt * 8 + 2 * tg;
        int f = col >> 1;
        float iv = sInv[f];
        int ta = t0 + g, tb = t0 + g + 8;
        float sn0, cs0, sn1, cs1;
        sincosf((float)ta * iv, &sn0, &cs0);
        sincosf((float)tb * iv, &sn1, &cs1);
        float* k0p = Ko + ((size_t)h * T_TOK + ta) * 64;
        float* k1p = Ko + ((size_t)h * T_TOK + tb) * 64;
        k0p[f]      = c[nt][0] * cs0 - c[nt][1] * sn0;
        k0p[f + 32] = c[nt][0] * sn0 + c[nt][1] * cs0;
        k1p[f]      = c[nt][2] * cs1 - c[nt][3] * sn1;
        k1p[f + 32] = c[nt][2] * sn1 + c[nt][3] * cs1;
    }
}

// ---------------------------------------------------------------------------
// Output projection, single tf32, split-K (validated r6/r7).
// ---------------------------------------------------------------------------
template<int SPLITK>
__global__ __launch_bounds__(256)
void mma_gemm_nn(const float* __restrict__ Ag, const float* __restrict__ Bg,
                 float* __restrict__ Cg, int M, int N, int K)
{
    __shared__ float As[16][132];
    __shared__ float Bs[16][132];
    int tid = threadIdx.x;
    int warp = tid >> 5, lane = tid & 31;
    int wm = warp >> 2, wn = warp & 3;
    int g = lane >> 2, tg = lane & 3;
    int m0 = blockIdx.y * 128, n0 = blockIdx.x * 128;
    int kchunk = K / SPLITK;
    int kbeg = blockIdx.z * kchunk;
    int kend = kbeg + kchunk;

    float c[4][4][4];
#pragma unroll
    for (int i = 0; i < 4; ++i)
#pragma unroll
        for (int j = 0; j < 4; ++j)
#pragma unroll
            for (int r = 0; r < 4; ++r) c[i][j][r] = 0.f;

    for (int k0 = kbeg; k0 < kend; k0 += 16) {
#pragma unroll
        for (int q = 0; q < 2; ++q) {
            int idx = q * 256 + tid;
            int row = idx >> 2, kq = (idx & 3) << 2;
            float4 a = *reinterpret_cast<const float4*>(Ag + (size_t)(m0 + row) * K + k0 + kq);
            As[kq + 0][row] = tf32r(a.x); As[kq + 1][row] = tf32r(a.y);
            As[kq + 2][row] = tf32r(a.z); As[kq + 3][row] = tf32r(a.w);
        }
#pragma unroll
        for (int q = 0; q < 2; ++q) {
            int idx = q * 256 + tid;
            int r = idx >> 5, ccol = (idx & 31) << 2;
            float4 b = *reinterpret_cast<const float4*>(Bg + (size_t)(k0 + r) * N + n0 + ccol);
            Bs[r][ccol + 0] = tf32r(b.x); Bs[r][ccol + 1] = tf32r(b.y);
            Bs[r][ccol + 2] = tf32r(b.z); Bs[r][ccol + 3] = tf32r(b.w);
        }
        __syncthreads();
#pragma unroll
        for (int h8 = 0; h8 < 16; h8 += 8) {
            uint32_t af[4][4], bf[4][2];
#pragma unroll
            for (int mt = 0; mt < 4; ++mt) {
                int mb = wm * 64 + mt * 16;
                af[mt][0] = __float_as_uint(As[h8 + tg][mb + g]);
                af[mt][1] = __float_as_uint(As[h8 + tg][mb + g + 8]);
                af[mt][2] = __float_as_uint(As[h8 + tg + 4][mb + g]);
                af[mt][3] = __float_as_uint(As[h8 + tg + 4][mb + g + 8]);
            }
#pragma unroll
            for (int nt = 0; nt < 4; ++nt) {
                int nb = wn * 32 + nt * 8;
                bf[nt][0] = __float_as_uint(Bs[h8 + tg][nb + g]);
                bf[nt][1] = __float_as_uint(Bs[h8 + tg + 4][nb + g]);
            }
#pragma unroll
            for (int mt = 0; mt < 4; ++mt)
#pragma unroll
                for (int nt = 0; nt < 4; ++nt) mma8(c[mt][nt], af[mt], bf[nt]);
        }
        __syncthreads();
    }

    float* Cp = Cg + (size_t)blockIdx.z * M * N;
#pragma unroll
    for (int mt = 0; mt < 4; ++mt) {
        int row = m0 + wm * 64 + mt * 16 + g;
#pragma unroll
        for (int nt = 0; nt < 4; ++nt) {
            int col = n0 + wn * 32 + nt * 8 + 2 * tg;
            *reinterpret_cast<float2*>(Cp + (size_t)row * N + col)
                = make_float2(c[mt][nt][0], c[mt][nt][1]);
            *reinterpret_cast<float2*>(Cp + (size_t)(row + 8) * N + col)
                = make_float2(c[mt][nt][2], c[mt][nt][3]);
        }
    }
}

// ---------------------------------------------------------------------------
// Block means -> block scores -> causal top-8 bitmask (validated r5-r7).
// ---------------------------------------------------------------------------
__global__ __launch_bounds__(256)
void blockstats_kernel(const float* __restrict__ Q, const float* __restrict__ K,
                       unsigned long long* __restrict__ maskbits)
{
    int h = blockIdx.x, tid = threadIdx.x;
    __shared__ float qm[64][64];
    __shared__ float kmT[64][64];
    __shared__ float sc[64][64];

    for (int idx = tid; idx < 4096; idx += 256) {
        int blk = idx >> 6, d = idx & 63;
        const float* Qp = Q + ((size_t)h * T_TOK + blk * 16) * 64 + d;
        const float* Kp = K + ((size_t)h * T_TOK + blk * 16) * 64 + d;
        float sq = 0.f, sk = 0.f;
#pragma unroll
        for (int l = 0; l < 16; ++l) { sq += Qp[l * 64]; sk += Kp[l * 64]; }
        qm[blk][d] = sq * 0.0625f;
        kmT[d][blk] = sk * 0.0625f;
    }
    __syncthreads();
    for (int idx = tid; idx < 4096; idx += 256) {
        int r = idx >> 6, c = idx & 63;
        float s = 0.f;
#pragma unroll
        for (int d = 0; d < 64; ++d) s += qm[r][d] * kmT[d][c];
        sc[r][c] = s;
    }
    __syncthreads();
    if (tid < 64) {
        int r = tid;
        unsigned long long bits = 0ull;
        int nsel = (r + 1 < 8) ? (r + 1) : 8;
        for (int sel = 0; sel < nsel; ++sel) {
            float best = -1e38f; int bi = 0;
            for (int kb = 0; kb <= r; ++kb) {
                float v = sc[r][kb];
                if (v > best) { best = v; bi = kb; }
            }
            sc[r][bi] = -1e38f;
            bits |= (1ull << bi);
        }
        maskbits[h * NB + r] = bits;
    }
}

// ---------------------------------------------------------------------------
// Sparse flash attention on tensor cores, v8: K/V staged through per-warp
// smem with coalesced float4 loads (was: scalar strided LDGs).
// One WARP per (head, qb).
// ---------------------------------------------------------------------------
__global__ __launch_bounds__(128)
void attn_mma(const float* __restrict__ Q, const float* __restrict__ K,
              const float* __restrict__ Vraw, const unsigned long long* __restrict__ maskbits,
              const float* __restrict__ sink_scalars, const float* __restrict__ v_nulls,
              float* __restrict__ ctx)
{
    int warp = threadIdx.x >> 5, lane = threadIdx.x & 31;
    int g = lane >> 2, tg = lane & 3;
    int idx = blockIdx.x * 4 + warp;
    int h = idx >> 6, qb = idx & 63;
    int s = h & 7;
    __shared__ __align__(16) float Ksm[4][16][68];
    __shared__ __align__(16) float Vsm[4][16][68];
    __shared__ float psm[4][16][20];

    // Q a-fragments, hi/lo
    uint32_t qh[8][4], ql[8][4];
    {
        const float* Qp = Q + ((size_t)h * T_TOK + qb * 16) * 64;
#pragma unroll
        for (int ks = 0; ks < 8; ++ks) {
            float a0 = Qp[g * 64 + ks * 8 + tg];
            float a1 = Qp[(g + 8) * 64 + ks * 8 + tg];
            float a2 = Qp[g * 64 + ks * 8 + tg + 4];
            float a3 = Qp[(g + 8) * 64 + ks * 8 + tg + 4];
            float h0 = tf32r(a0), h1 = tf32r(a1), h2 = tf32r(a2), h3 = tf32r(a3);
            qh[ks][0] = __float_as_uint(h0); ql[ks][0] = __float_as_uint(tf32r(a0 - h0));
            qh[ks][1] = __float_as_uint(h1); ql[ks][1] = __float_as_uint(tf32r(a1 - h1));
            qh[ks][2] = __float_as_uint(h2); ql[ks][2] = __float_as_uint(tf32r(a2 - h2));
            qh[ks][3] = __float_as_uint(h3); ql[ks][3] = __float_as_uint(tf32r(a3 - h3));
        }
    }

    float c[8][4];
#pragma unroll
    for (int nt = 0; nt < 8; ++nt)
#pragma unroll
        for (int r = 0; r < 4; ++r) c[nt][r] = 0.f;

    float m0 = NEGBIG, m1 = NEGBIG, l0 = 0.f, l1 = 0.f;
    unsigned long long bm = maskbits[h * NB + qb];
    int i0 = qb * 16 + g, i1 = i0 + 8;

    for (int kb = 0; kb <= qb; ++kb) {
        bool blk_ok = ((bm >> kb) & 1ull) || (kb < 4) || (kb == qb);
        if (!blk_ok && kb != qb - 1) continue;

        // stage K (16x64) and V (16x64) tiles: coalesced float4 loads
        {
            const float* Kp = K + ((size_t)h * T_TOK + kb * 16) * 64;
            const float* Vp = Vraw + (size_t)(kb * 16) * 512 + s * 64;
            __syncwarp();
#pragma unroll
            for (int i = 0; i < 8; ++i) {
                int lin = i * 32 + lane;          // 0..255
                int row = lin >> 4, c4 = (lin & 15) << 2;
                *reinterpret_cast<float4*>(&Ksm[warp][row][c4]) =
                    *reinterpret_cast<const float4*>(Kp + row * 64 + c4);
                *reinterpret_cast<float4*>(&Vsm[warp][row][c4]) =
                    *reinterpret_cast<const float4*>(Vp + (size_t)row * 512 + c4);
            }
            __syncwarp();
        }

        // S = Q @ K^T  (16x16), 3xTF32
        float sc[2][4];
#pragma unroll
        for (int nt = 0; nt < 2; ++nt)
#pragma unroll
            for (int r = 0; r < 4; ++r) sc[nt][r] = 0.f;

#pragma unroll
        for (int ks = 0; ks < 8; ++ks) {
#pragma unroll
            for (int nt = 0; nt < 2; ++nt) {
                float b0f = Ksm[warp][nt * 8 + g][ks * 8 + tg];
                float b1f = Ksm[warp][nt * 8 + g][ks * 8 + tg + 4];
                float bh0 = tf32r(b0f), bh1 = tf32r(b1f);
                uint32_t bh[2] = { __float_as_uint(bh0), __float_as_uint(bh1) };
                uint32_t bl[2] = { __float_as_uint(tf32r(b0f - bh0)),
                                   __float_as_uint(tf32r(b1f - bh1)) };
                mma8(sc[nt], qh[ks], bh);
                mma8(sc[nt], qh[ks], bl);
                mma8(sc[nt], ql[ks], bh);
            }
        }

        // scale + mask
#pragma unroll
        for (int nt = 0; nt < 2; ++nt)
#pragma unroll
            for (int r = 0; r < 4; ++r) {
                int j = kb * 16 + nt * 8 + 2 * tg + (r & 1);
                int i = (r < 2) ? i0 : i1;
                float v = sc[nt][r] * 0.125f;
                bool valid = (j <= i) && (blk_ok || (j >= i - 16));
                sc[nt][r] = valid ? v : NEGBIG;
            }

        // online softmax (quad reduce)
        float mx0 = fmaxf(fmaxf(sc[0][0], sc[0][1]), fmaxf(sc[1][0], sc[1][1]));
        float mx1 = fmaxf(fmaxf(sc[0][2], sc[0][3]), fmaxf(sc[1][2], sc[1][3]));
        mx0 = fmaxf(mx0, __shfl_xor_sync(0xffffffffu, mx0, 1));
        mx0 = fmaxf(mx0, __shfl_xor_sync(0xffffffffu, mx0, 2));
        mx1 = fmaxf(mx1, __shfl_xor_sync(0xffffffffu, mx1, 1));
        mx1 = fmaxf(mx1, __shfl_xor_sync(0xffffffffu, mx1, 2));
        float mn0 = fmaxf(m0, mx0), mn1 = fmaxf(m1, mx1);
        float al0 = __expf(m0 - mn0), al1 = __expf(m1 - mn1);
        m0 = mn0; m1 = mn1;

        float p[2][4];
#pragma unroll
        for (int nt = 0; nt < 2; ++nt) {
            p[nt][0] = __expf(sc[nt][0] - mn0);
            p[nt][1] = __expf(sc[nt][1] - mn0);
            p[nt][2] = __expf(sc[nt][2] - mn1);
            p[nt][3] = __expf(sc[nt][3] - mn1);
        }
        float s0 = p[0][0] + p[0][1] + p[1][0] + p[1][1];
        float s1 = p[0][2] + p[0][3] + p[1][2] + p[1][3];
        s0 += __shfl_xor_sync(0xffffffffu, s0, 1);
        s0 += __shfl_xor_sync(0xffffffffu, s0, 2);
        s1 += __shfl_xor_sync(0xffffffffu, s1, 1);
        s1 += __shfl_xor_sync(0xffffffffu, s1, 2);
        l0 = l0 * al0 + s0;
        l1 = l1 * al1 + s1;

        // rescale ctx accumulators
#pragma unroll
        for (int nt = 0; nt < 8; ++nt) {
            c[nt][0] *= al0; c[nt][1] *= al0;
            c[nt][2] *= al1; c[nt][3] *= al1;
        }

        // P -> a-frag layout via per-warp smem
        __syncwarp();
#pragma unroll
        for (int nt = 0; nt < 2; ++nt) {
            psm[warp][g][nt * 8 + 2 * tg]         = p[nt][0];
            psm[warp][g][nt * 8 + 2 * tg + 1]     = p[nt][1];
            psm[warp][g + 8][nt * 8 + 2 * tg]     = p[nt][2];
            psm[warp][g + 8][nt * 8 + 2 * tg + 1] = p[nt][3];
        }
        __syncwarp();
        uint32_t pah[2][4], pal[2][4];
#pragma unroll
        for (int ks = 0; ks < 2; ++ks) {
            float a0 = psm[warp][g][ks * 8 + tg];
            float a1 = psm[warp][g + 8][ks * 8 + tg];
            float a2 = psm[warp][g][ks * 8 + tg + 4];
            float a3 = psm[warp][g + 8][ks * 8 + tg + 4];
            float h0 = tf32r(a0), h1 = tf32r(a1), h2 = tf32r(a2), h3 = tf32r(a3);
            pah[ks][0] = __float_as_uint(h0); pal[ks][0] = __float_as_uint(tf32r(a0 - h0));
            pah[ks][1] = __float_as_uint(h1); pal[ks][1] = __float_as_uint(tf32r(a1 - h1));
            pah[ks][2] = __float_as_uint(h2); pal[ks][2] = __float_as_uint(tf32r(a2 - h2));
            pah[ks][3] = __float_as_uint(h3); pal[ks][3] = __float_as_uint(tf32r(a3 - h3));
        }

        // ctx += P @ V  (16x64), 3xTF32, V from smem
#pragma unroll
        for (int nt = 0; nt < 8; ++nt) {
#pragma unroll
            for (int ks = 0; ks < 2; ++ks) {
                float b0f = Vsm[warp][ks * 8 + tg][nt * 8 + g];
                float b1f = Vsm[warp][ks * 8 + tg + 4][nt * 8 + g];
                float bh0 = tf32r(b0f), bh1 = tf32r(b1f);
                uint32_t bh[2] = { __float_as_uint(bh0), __float_as_uint(bh1) };
                uint32_t bl[2] = { __float_as_uint(tf32r(b0f - bh0)),
                                   __float_as_uint(tf32r(b1f - bh1)) };
                mma8(c[nt], pah[ks], bh);
                mma8(c[nt], pah[ks], bl);
                mma8(c[nt], pal[ks], bh);
            }
        }
    }

    // sink + normalize + writeout
    float sv = sink_scalars[h];
    float fn0 = fmaxf(m0, sv), fn1 = fmaxf(m1, sv);
    float fa0 = __expf(m0 - fn0), fa1 = __expf(m1 - fn1);
    float pk0 = __expf(sv - fn0), pk1 = __expf(sv - fn1);
    float inv0 = 1.f / (l0 * fa0 + pk0);
    float inv1 = 1.f / (l1 * fa1 + pk1);
    const float* vn = v_nulls + h * 64;
#pragma unroll
    for (int nt = 0; nt < 8; ++nt) {
        int col = nt * 8 + 2 * tg;
        float vn0 = vn[col], vn1 = vn[col + 1];
        float* op0 = ctx + (size_t)(qb * 16 + g) * 4096 + h * 64 + col;
        float* op1 = ctx + (size_t)(qb * 16 + g + 8) * 4096 + h * 64 + col;
        *reinterpret_cast<float2*>(op0) =
            make_float2((c[nt][0] * fa0 + pk0 * vn0) * inv0,
                        (c[nt][1] * fa0 + pk0 * vn1) * inv0);
        *reinterpret_cast<float2*>(op1) =
            make_float2((c[nt][2] * fa1 + pk1 * vn0) * inv1,
                        (c[nt][3] * fa1 + pk1 * vn1) * inv1);
    }
}

// ---------------------------------------------------------------------------
__global__ void reduce_out(const float* __restrict__ part, const float* __restrict__ WOb,
                           float* __restrict__ out)
{
    int idx = blockIdx.x * 256 + threadIdx.x;
    int col = idx & 511;
    float b = 0.f;
#pragma unroll
    for (int n = 0; n < 8; ++n) b += WOb[n * 512 + col];
    const int S = T_TOK * 512;
    out[idx] = 0.125f * (part[idx] + part[S + idx] + part[2 * S + idx] + part[3 * S + idx] + b);
}

// ---------------------------------------------------------------------------
extern "C" void kernel_launch(void* const* d_in, const int* in_sizes, int n_in,
                              void* d_out, int out_size)
{
    const float* x   = (const float*)d_in[0];
    const float* WQ  = (const float*)d_in[1];
    const float* WK  = (const float*)d_in[2];
    const float* bK  = (const float*)d_in[3];
    const float* WV  = (const float*)d_in[4];
    const float* bV  = (const float*)d_in[5];
    const float* Am  = (const float*)d_in[6];
    const float* idb = (const float*)d_in[7];
    const float* snk = (const float*)d_in[8];
    const float* vnl = (const float*)d_in[9];
    const float* WO  = (const float*)d_in[10];
    const float* WOb = (const float*)d_in[11];
    float* out = (float*)d_out;

    float *weff, *kraw, *vraw, *Qb, *Kb, *ctx, *part;
    unsigned long long* mb;
    cudaGetSymbolAddress((void**)&weff, g_Weff);
    cudaGetSymbolAddress((void**)&kraw, g_kraw);
    cudaGetSymbolAddress((void**)&vraw, g_vraw);
    cudaGetSymbolAddress((void**)&Qb,   g_Q);
    cudaGetSymbolAddress((void**)&Kb,   g_K);
    cudaGetSymbolAddress((void**)&ctx,  g_ctx);
    cudaGetSymbolAddress((void**)&part, g_part);
    cudaGetSymbolAddress((void**)&mb,   g_mask);

    prep_misc<<<1024, 256>>>(WK, WV, weff);
    prep_fold<<<dim3(64, 4), 128>>>(Am, idb, WQ, weff);

    qkv_gemm<<<dim3(40, 8), 256>>>(x, weff, bK, bV, Qb, kraw, vraw);
    ktrans_rope<<<dim3(8, 64), 256>>>(Am, idb, kraw, Kb);

    blockstats_kernel<<<64, 256>>>(Qb, Kb, mb);
    attn_mma<<<1024, 128>>>(Qb, Kb, vraw, mb, snk, vnl, ctx);

    mma_gemm_nn<4><<<dim3(4, 8, 4), 256>>>(ctx, WO, part, 1024, 512, 4096);
    reduce_out<<<2048, 256>>>(part, WOb, out);
}